// round 3
// baseline (speedup 1.0000x reference)
#include <cuda_runtime.h>
#include <math.h>
#include <stdint.h>

#define DINLINE __device__ __forceinline__

// ---------------- problem constants ----------------
constexpr int Bb = 4;
constexpr int Sq = 4096;
constexpr int Hd = 1024;
constexpr int Id = 512;
constexpr int En = 16;
constexpr int NE = 15;           // routed (non-identity) experts
constexpr int Tn = Bb * Sq;      // 16384 tokens
constexpr int SP = Sq + 2;       // padded seq for conv
constexpr int MAXROWS = 2 * Tn + NE * 128;   // 34688 (128-aligned segments)
constexpr int MAX_TILES = MAXROWS / 128;     // 271

// ---------------- device scratch (static: no allocations allowed) ----------------
__device__ __align__(16) float g_xpad[Bb * SP * Hd];        // ~67 MB
__device__ __align__(16) float g_wp[3 * Hd * Id];           // conv weights relaid (3072 x 512)
__device__ __align__(16) float g_shact[Tn * Id];            // shared gate -> act (in place)
__device__ __align__(16) float g_act[(size_t)MAXROWS * Id]; // routed gate -> act (in place)

__device__ int   g_top_idx[Tn * 2];
__device__ float g_top_w[Tn * 2];
__device__ float g_wid[Tn];
__device__ int   g_counts[NE];
__device__ int   g_cursor[NE];
__device__ int   g_off[NE + 1];
__device__ int   g_tile_expert[MAX_TILES];
__device__ int   g_ntiles;
__device__ int   g_as_tok[MAXROWS];
__device__ float g_as_w[MAXROWS];

// ---------------- f32x2 packed helpers (Blackwell) ----------------
typedef unsigned long long u64;
DINLINE u64 pack2(float lo, float hi) {
    u64 r; asm("mov.b64 %0,{%1,%2};" : "=l"(r) : "f"(lo), "f"(hi)); return r;
}
DINLINE void unpack2(u64 v, float& lo, float& hi) {
    asm("mov.b64 {%0,%1},%2;" : "=f"(lo), "=f"(hi) : "l"(v));
}
DINLINE void fma2(u64& d, u64 a, u64 b) {
    asm("fma.rn.f32x2 %0,%1,%2,%0;" : "+l"(d) : "l"(a), "l"(b));
}

DINLINE float silu_f(float g) { return g / (1.f + expf(-g)); }

// ---------------- small kernels ----------------
__global__ void zero_meta() {
    int t = threadIdx.x;
    if (t < NE) { g_counts[t] = 0; g_cursor[t] = 0; }
}

// one warp per token: logits (fp32 exact path for routing), softmax, top-2
__global__ void router_kernel(const float* __restrict__ x,
                              const float* __restrict__ rw,
                              const float* __restrict__ rb) {
    int gw = (blockIdx.x * blockDim.x + threadIdx.x) >> 5;
    int lane = threadIdx.x & 31;
    if (gw >= Tn) return;
    const float* xr = x + (size_t)gw * Hd;
    float acc[16];
#pragma unroll
    for (int e = 0; e < 16; e++) acc[e] = 0.f;
    for (int h = lane; h < Hd; h += 32) {
        float xv = xr[h];
        const float4* w4 = (const float4*)(rw + (size_t)h * 16);
        float4 w0 = w4[0], w1 = w4[1], w2 = w4[2], w3 = w4[3];
        acc[0]  += xv * w0.x; acc[1]  += xv * w0.y; acc[2]  += xv * w0.z; acc[3]  += xv * w0.w;
        acc[4]  += xv * w1.x; acc[5]  += xv * w1.y; acc[6]  += xv * w1.z; acc[7]  += xv * w1.w;
        acc[8]  += xv * w2.x; acc[9]  += xv * w2.y; acc[10] += xv * w2.z; acc[11] += xv * w2.w;
        acc[12] += xv * w3.x; acc[13] += xv * w3.y; acc[14] += xv * w3.z; acc[15] += xv * w3.w;
    }
#pragma unroll
    for (int e = 0; e < 16; e++) {
#pragma unroll
        for (int o = 16; o > 0; o >>= 1) acc[e] += __shfl_xor_sync(0xffffffffu, acc[e], o);
    }
    if (lane == 0) {
        float l[16]; float m = -1e30f;
#pragma unroll
        for (int e = 0; e < 16; e++) { l[e] = acc[e] + rb[e]; m = fmaxf(m, l[e]); }
        float p[16]; float s = 0.f;
#pragma unroll
        for (int e = 0; e < 16; e++) { p[e] = expf(l[e] - m); s += p[e]; }
        int i1 = 0; float p1 = p[0];
#pragma unroll
        for (int e = 1; e < 16; e++) if (p[e] > p1) { p1 = p[e]; i1 = e; }
        int i2 = -1; float p2 = -1e30f;
#pragma unroll
        for (int e = 0; e < 16; e++) if (e != i1 && p[e] > p2) { p2 = p[e]; i2 = e; }
        float pr1 = p1 / s, pr2 = p2 / s;
        float d = pr1 + pr2 + 1e-6f;
        float w1 = pr1 / d, w2 = pr2 / d;
        g_top_idx[gw * 2] = i1; g_top_idx[gw * 2 + 1] = i2;
        g_top_w[gw * 2] = w1;   g_top_w[gw * 2 + 1] = w2;
        float wid = 0.f;
        if (i1 == NE) wid = w1; else if (i2 == NE) wid = w2;
        g_wid[gw] = wid;
        if (i1 < NE) atomicAdd(&g_counts[i1], 1);
        if (i2 < NE) atomicAdd(&g_counts[i2], 1);
    }
}

__global__ void prefix_kernel() {
    if (threadIdx.x == 0 && blockIdx.x == 0) {
        int off = 0;
        for (int e = 0; e < NE; e++) {
            g_off[e] = off;
            int a = (g_counts[e] + 127) & ~127;
            int t0 = off >> 7, t1 = (off + a) >> 7;
            for (int t = t0; t < t1; t++) g_tile_expert[t] = e;
            off += a;
        }
        g_off[NE] = off;
        g_ntiles = off >> 7;
    }
}

__global__ void fill_assign() {
    int i = blockIdx.x * blockDim.x + threadIdx.x;
    if (i < MAXROWS) { g_as_tok[i] = 0; g_as_w[i] = 0.f; }
}

__global__ void assign_kernel() {
    int t = blockIdx.x * blockDim.x + threadIdx.x;
    if (t >= Tn) return;
#pragma unroll
    for (int k = 0; k < 2; k++) {
        int e = g_top_idx[t * 2 + k];
        if (e < NE) {
            int p = atomicAdd(&g_cursor[e], 1);
            int r = g_off[e] + p;
            g_as_tok[r] = t;
            g_as_w[r] = g_top_w[t * 2 + k];
        }
    }
}

// Xpad[b][j][h] = x[b][j-2][h] (zeros for j<2) -> conv becomes one K=3072 GEMM
__global__ void build_xpad(const float* __restrict__ x) {
    int i = blockIdx.x * blockDim.x + threadIdx.x;
    if (i >= Bb * SP * Hd) return;
    int h = i % Hd;
    int r = (i / Hd) % SP;
    int b = i / (Hd * SP);
    g_xpad[i] = (r < 2) ? 0.f : x[((size_t)(b * Sq + (r - 2))) * Hd + h];
}

// Wp[(k*H+h)][i] = conv_w[i][h][k]   (conv_w shape (I,H,KS) row-major)
__global__ void build_wp(const float* __restrict__ cw) {
    int i = blockIdx.x * blockDim.x + threadIdx.x;
    if (i >= 3 * Hd * Id) return;
    int ii = i % Id;
    int h = (i / Id) % Hd;
    int k = i / (Id * Hd);
    g_wp[i] = cw[(size_t)ii * (Hd * 3) + h * 3 + k];
}

// ---------------- SGEMM (fp32, f32x2-packed FMA) ----------------
enum { M_SH_GATE = 0, M_SH_UP, M_SH_DOWN, M_R_GATE, M_R_UP, M_R_DOWN };

template <int MODE>
__global__ void __launch_bounds__(256) sgemm_k(const float* __restrict__ X,
                                               const float* __restrict__ W,
                                               float* __restrict__ OUT) {
    constexpr int KD = (MODE == M_SH_GATE) ? 3 * Hd
                     : ((MODE == M_SH_DOWN || MODE == M_R_DOWN) ? Id : Hd);
    constexpr int ND = (MODE == M_SH_DOWN || MODE == M_R_DOWN) ? Hd : Id;
    constexpr int BM = 128, BN = 128, BK = 16;
    constexpr int PITCH = 132;

    int tileM = blockIdx.x;
    if constexpr (MODE >= M_R_GATE) {
        if (tileM >= g_ntiles) return;
    }
    int nb = blockIdx.y;
    int tid = threadIdx.x;

    __shared__ float sA[BK * PITCH];
    __shared__ float sB[BK * PITCH];

    // B base (per-expert slice for routed modes)
    const float* Bbase;
    if constexpr (MODE == M_SH_GATE) {
        Bbase = g_wp; (void)W;
    } else if constexpr (MODE == M_SH_UP || MODE == M_SH_DOWN) {
        Bbase = W;
    } else {
        int e = g_tile_expert[tileM];
        Bbase = W + (size_t)e * Hd * Id;
    }

    // per-thread A/B global pointers (2 float4 loads each)
    const float* aptr[2];
#pragma unroll
    for (int j = 0; j < 2; j++) {
        int f = tid + 256 * j;
        int r = f >> 2, c4 = f & 3;
        int row = tileM * BM + r;
        const float* p;
        if constexpr (MODE == M_SH_GATE) {
            int b = row >> 12, s = row & (Sq - 1);
            p = g_xpad + (size_t)(b * SP + s) * Hd;
        } else if constexpr (MODE == M_SH_UP) {
            p = X + (size_t)row * Hd;
        } else if constexpr (MODE == M_SH_DOWN) {
            p = g_shact + (size_t)row * Id;
        } else if constexpr (MODE == M_R_GATE || MODE == M_R_UP) {
            p = X + (size_t)g_as_tok[row] * Hd;
        } else {
            p = g_act + (size_t)row * Id;
        }
        aptr[j] = p + c4 * 4;
    }
    const float* bptr[2];
#pragma unroll
    for (int j = 0; j < 2; j++) {
        int f = tid + 256 * j;
        int br = f >> 5, bc4 = f & 31;
        bptr[j] = Bbase + (size_t)br * ND + nb * BN + bc4 * 4;
    }

    u64 acc[4][8];
#pragma unroll
    for (int i = 0; i < 4; i++)
#pragma unroll
        for (int j = 0; j < 8; j++) acc[i][j] = 0ull;  // (+0.f, +0.f)

    int ty = tid >> 4, tx = tid & 15;

    float4 rA[2], rB[2];
#pragma unroll
    for (int j = 0; j < 2; j++) {
        rA[j] = *(const float4*)(aptr[j]);
        rB[j] = *(const float4*)(bptr[j]);
    }

    for (int kt = 0; kt < KD; kt += BK) {
        __syncthreads();
#pragma unroll
        for (int j = 0; j < 2; j++) {
            int f = tid + 256 * j;
            int r = f >> 2, c4 = f & 3;
            sA[(c4 * 4 + 0) * PITCH + r] = rA[j].x;
            sA[(c4 * 4 + 1) * PITCH + r] = rA[j].y;
            sA[(c4 * 4 + 2) * PITCH + r] = rA[j].z;
            sA[(c4 * 4 + 3) * PITCH + r] = rA[j].w;
            int br = f >> 5, bc4 = f & 31;
            *(float4*)&sB[br * PITCH + bc4 * 4] = rB[j];
        }
        __syncthreads();
        if (kt + BK < KD) {
#pragma unroll
            for (int j = 0; j < 2; j++) {
                rA[j] = *(const float4*)(aptr[j] + (kt + BK));
                rB[j] = *(const float4*)(bptr[j] + (size_t)(kt + BK) * ND);
            }
        }
#pragma unroll
        for (int k = 0; k < BK; k++) {
            float4 a0 = *(const float4*)&sA[k * PITCH + ty * 8];
            float4 a1 = *(const float4*)&sA[k * PITCH + ty * 8 + 4];
            u64 A2[4];
            A2[0] = pack2(a0.x, a0.y);
            A2[1] = pack2(a0.z, a0.w);
            A2[2] = pack2(a1.x, a1.y);
            A2[3] = pack2(a1.z, a1.w);
            float4 b0 = *(const float4*)&sB[k * PITCH + tx * 8];
            float4 b1 = *(const float4*)&sB[k * PITCH + tx * 8 + 4];
            float bf[8] = {b0.x, b0.y, b0.z, b0.w, b1.x, b1.y, b1.z, b1.w};
#pragma unroll
            for (int j = 0; j < 8; j++) {
                u64 bb = pack2(bf[j], bf[j]);
#pragma unroll
                for (int i = 0; i < 4; i++) fma2(acc[i][j], A2[i], bb);
            }
        }
    }

    // ---------------- epilogue ----------------
    int row0 = tileM * BM + ty * 8;
    int col0 = nb * BN + tx * 8;
#pragma unroll
    for (int i2 = 0; i2 < 4; i2++) {
        float v[2][8];
#pragma unroll
        for (int j = 0; j < 8; j++) unpack2(acc[i2][j], v[0][j], v[1][j]);
#pragma unroll
        for (int h = 0; h < 2; h++) {
            int row = row0 + i2 * 2 + h;
            if constexpr (MODE == M_SH_GATE) {
                float* dst = g_shact + (size_t)row * Id + col0;
#pragma unroll
                for (int j = 0; j < 8; j++) dst[j] = v[h][j];
            } else if constexpr (MODE == M_SH_UP) {
                float* dst = g_shact + (size_t)row * Id + col0;
#pragma unroll
                for (int j = 0; j < 8; j++) {
                    float g = dst[j];
                    dst[j] = silu_f(g) * v[h][j];
                }
            } else if constexpr (MODE == M_SH_DOWN) {
                const float* xr = X + (size_t)row * Hd + col0;
                float w = g_wid[row];
                float* dst = OUT + (size_t)row * Hd + col0;
#pragma unroll
                for (int j = 0; j < 8; j++) dst[j] = v[h][j] + w * xr[j];
            } else if constexpr (MODE == M_R_GATE) {
                float* dst = g_act + (size_t)row * Id + col0;
#pragma unroll
                for (int j = 0; j < 8; j++) dst[j] = v[h][j];
            } else if constexpr (MODE == M_R_UP) {
                float* dst = g_act + (size_t)row * Id + col0;
#pragma unroll
                for (int j = 0; j < 8; j++) {
                    float g = dst[j];
                    dst[j] = silu_f(g) * v[h][j];
                }
            } else {  // M_R_DOWN
                float w = g_as_w[row];
                if (w != 0.f) {
                    int tok = g_as_tok[row];
                    float* dst = OUT + (size_t)tok * Hd + col0;
#pragma unroll
                    for (int j = 0; j < 8; j++) atomicAdd(dst + j, w * v[h][j]);
                }
            }
        }
    }
}

// ---------------- launch ----------------
extern "C" void kernel_launch(void* const* d_in, const int* in_sizes, int n_in,
                              void* d_out, int out_size) {
    (void)in_sizes; (void)n_in; (void)out_size;
    const float* x   = (const float*)d_in[0];  // hidden_states (B,S,H)
    const float* rw  = (const float*)d_in[1];  // router_w (H,E)
    const float* rb  = (const float*)d_in[2];  // router_bias (E)
    const float* gw  = (const float*)d_in[3];  // expert_gate_w (E-1,H,I)
    const float* uw  = (const float*)d_in[4];  // expert_up_w (E-1,H,I)
    const float* dw  = (const float*)d_in[5];  // expert_down_w (E-1,I,H)
    const float* cw  = (const float*)d_in[6];  // conv_w (I,H,KS)
    const float* suw = (const float*)d_in[7];  // shared_up_w (H,I)
    const float* sdw = (const float*)d_in[8];  // shared_down_w (I,H)
    float* out = (float*)d_out;

    zero_meta<<<1, 32>>>();
    router_kernel<<<Tn / 8, 256>>>(x, rw, rb);
    prefix_kernel<<<1, 32>>>();
    fill_assign<<<(MAXROWS + 255) / 256, 256>>>();
    assign_kernel<<<Tn / 256, 256>>>();
    build_xpad<<<(Bb * SP * Hd + 255) / 256, 256>>>(x);
    build_wp<<<(3 * Hd * Id + 255) / 256, 256>>>(cw);

    // shared expert: gate(conv as K=3072 GEMM) -> up(*silu gate) -> down(+identity)
    sgemm_k<M_SH_GATE><<<dim3(Tn / 128, Id / 128), 256>>>(x, nullptr, nullptr);
    sgemm_k<M_SH_UP><<<dim3(Tn / 128, Id / 128), 256>>>(x, suw, nullptr);
    sgemm_k<M_SH_DOWN><<<dim3(Tn / 128, Hd / 128), 256>>>(x, sdw, out);

    // routed experts on gathered, 128-aligned segments
    sgemm_k<M_R_GATE><<<dim3(MAX_TILES, Id / 128), 256>>>(x, gw, nullptr);
    sgemm_k<M_R_UP><<<dim3(MAX_TILES, Id / 128), 256>>>(x, uw, nullptr);
    sgemm_k<M_R_DOWN><<<dim3(MAX_TILES, Hd / 128), 256>>>(x, dw, out);
}

// round 4
// speedup vs baseline: 1.0006x; 1.0006x over previous
#include <cuda_runtime.h>
#include <math.h>
#include <stdint.h>

#define DINLINE __device__ __forceinline__

// ---------------- problem constants ----------------
constexpr int Bb = 4;
constexpr int Sq = 4096;
constexpr int Hd = 1024;
constexpr int Id = 512;
constexpr int En = 16;
constexpr int NE = 15;           // routed (non-identity) experts
constexpr int Tn = Bb * Sq;      // 16384 tokens
constexpr int SP = Sq + 2;       // padded seq for conv
constexpr int MAXROWS = 2 * Tn + NE * 128;   // 34688 (128-aligned segments)
constexpr int MAX_TILES = MAXROWS / 128;     // 271

// ---------------- device scratch (static: no allocations allowed) ----------------
__device__ __align__(16) float g_xpad[Bb * SP * Hd];        // ~67 MB
__device__ __align__(16) float g_wp[3 * Hd * Id];           // conv weights relaid (3072 x 512)
__device__ __align__(16) float g_shact[Tn * Id];            // shared gate -> act (in place)
__device__ __align__(16) float g_act[(size_t)MAXROWS * Id]; // routed gate -> act (in place)

__device__ int   g_top_idx[Tn * 2];
__device__ float g_top_w[Tn * 2];
__device__ float g_wid[Tn];
__device__ int   g_counts[NE];
__device__ int   g_cursor[NE];
__device__ int   g_off[NE + 1];
__device__ int   g_tile_expert[MAX_TILES];
__device__ int   g_ntiles;
__device__ int   g_as_tok[MAXROWS];
__device__ float g_as_w[MAXROWS];

// ---------------- f32x2 packed helpers (Blackwell) ----------------
typedef unsigned long long u64;
DINLINE u64 pack2(float lo, float hi) {
    u64 r; asm("mov.b64 %0,{%1,%2};" : "=l"(r) : "f"(lo), "f"(hi)); return r;
}
DINLINE void unpack2(u64 v, float& lo, float& hi) {
    asm("mov.b64 {%0,%1},%2;" : "=f"(lo), "=f"(hi) : "l"(v));
}
DINLINE void fma2(u64& d, u64 a, u64 b) {
    asm("fma.rn.f32x2 %0,%1,%2,%0;" : "+l"(d) : "l"(a), "l"(b));
}

DINLINE float silu_f(float g) { return g / (1.f + expf(-g)); }

// ---------------- small kernels ----------------
__global__ void zero_meta() {
    int t = threadIdx.x;
    if (t < NE) { g_counts[t] = 0; g_cursor[t] = 0; }
}

// one warp per token: logits (fp32 exact path for routing), softmax, top-2
__global__ void router_kernel(const float* __restrict__ x,
                              const float* __restrict__ rw,
                              const float* __restrict__ rb) {
    int gw = (blockIdx.x * blockDim.x + threadIdx.x) >> 5;
    int lane = threadIdx.x & 31;
    if (gw >= Tn) return;
    const float* xr = x + (size_t)gw * Hd;
    float acc[16];
#pragma unroll
    for (int e = 0; e < 16; e++) acc[e] = 0.f;
    for (int h = lane; h < Hd; h += 32) {
        float xv = xr[h];
        const float4* w4 = (const float4*)(rw + (size_t)h * 16);
        float4 w0 = w4[0], w1 = w4[1], w2 = w4[2], w3 = w4[3];
        acc[0]  += xv * w0.x; acc[1]  += xv * w0.y; acc[2]  += xv * w0.z; acc[3]  += xv * w0.w;
        acc[4]  += xv * w1.x; acc[5]  += xv * w1.y; acc[6]  += xv * w1.z; acc[7]  += xv * w1.w;
        acc[8]  += xv * w2.x; acc[9]  += xv * w2.y; acc[10] += xv * w2.z; acc[11] += xv * w2.w;
        acc[12] += xv * w3.x; acc[13] += xv * w3.y; acc[14] += xv * w3.z; acc[15] += xv * w3.w;
    }
#pragma unroll
    for (int e = 0; e < 16; e++) {
#pragma unroll
        for (int o = 16; o > 0; o >>= 1) acc[e] += __shfl_xor_sync(0xffffffffu, acc[e], o);
    }
    if (lane == 0) {
        float l[16]; float m = -1e30f;
#pragma unroll
        for (int e = 0; e < 16; e++) { l[e] = acc[e] + rb[e]; m = fmaxf(m, l[e]); }
        float p[16]; float s = 0.f;
#pragma unroll
        for (int e = 0; e < 16; e++) { p[e] = expf(l[e] - m); s += p[e]; }
        int i1 = 0; float p1 = p[0];
#pragma unroll
        for (int e = 1; e < 16; e++) if (p[e] > p1) { p1 = p[e]; i1 = e; }
        int i2 = -1; float p2 = -1e30f;
#pragma unroll
        for (int e = 0; e < 16; e++) if (e != i1 && p[e] > p2) { p2 = p[e]; i2 = e; }
        float pr1 = p1 / s, pr2 = p2 / s;
        float d = pr1 + pr2 + 1e-6f;
        float w1 = pr1 / d, w2 = pr2 / d;
        g_top_idx[gw * 2] = i1; g_top_idx[gw * 2 + 1] = i2;
        g_top_w[gw * 2] = w1;   g_top_w[gw * 2 + 1] = w2;
        float wid = 0.f;
        if (i1 == NE) wid = w1; else if (i2 == NE) wid = w2;
        g_wid[gw] = wid;
        if (i1 < NE) atomicAdd(&g_counts[i1], 1);
        if (i2 < NE) atomicAdd(&g_counts[i2], 1);
    }
}

__global__ void prefix_kernel() {
    if (threadIdx.x == 0 && blockIdx.x == 0) {
        int off = 0;
        for (int e = 0; e < NE; e++) {
            g_off[e] = off;
            int a = (g_counts[e] + 127) & ~127;
            int t0 = off >> 7, t1 = (off + a) >> 7;
            for (int t = t0; t < t1; t++) g_tile_expert[t] = e;
            off += a;
        }
        g_off[NE] = off;
        g_ntiles = off >> 7;
    }
}

__global__ void fill_assign() {
    int i = blockIdx.x * blockDim.x + threadIdx.x;
    if (i < MAXROWS) { g_as_tok[i] = 0; g_as_w[i] = 0.f; }
}

__global__ void assign_kernel() {
    int t = blockIdx.x * blockDim.x + threadIdx.x;
    if (t >= Tn) return;
#pragma unroll
    for (int k = 0; k < 2; k++) {
        int e = g_top_idx[t * 2 + k];
        if (e < NE) {
            int p = atomicAdd(&g_cursor[e], 1);
            int r = g_off[e] + p;
            g_as_tok[r] = t;
            g_as_w[r] = g_top_w[t * 2 + k];
        }
    }
}

// Xpad[b][j][h] = x[b][j-2][h] (zeros for j<2) -> conv becomes one K=3072 GEMM
__global__ void build_xpad(const float* __restrict__ x) {
    int i = blockIdx.x * blockDim.x + threadIdx.x;
    if (i >= Bb * SP * Hd) return;
    int h = i % Hd;
    int r = (i / Hd) % SP;
    int b = i / (Hd * SP);
    g_xpad[i] = (r < 2) ? 0.f : x[((size_t)(b * Sq + (r - 2))) * Hd + h];
}

// Wp[(k*H+h)][i] = conv_w[i][h][k]   (conv_w shape (I,H,KS) row-major)
__global__ void build_wp(const float* __restrict__ cw) {
    int i = blockIdx.x * blockDim.x + threadIdx.x;
    if (i >= 3 * Hd * Id) return;
    int ii = i % Id;
    int h = (i / Id) % Hd;
    int k = i / (Id * Hd);
    g_wp[i] = cw[(size_t)ii * (Hd * 3) + h * 3 + k];
}

// ---------------- SGEMM (fp32, f32x2-packed FMA) ----------------
enum { M_SH_GATE = 0, M_SH_UP, M_SH_DOWN, M_R_GATE, M_R_UP, M_R_DOWN };

template <int MODE>
__global__ void __launch_bounds__(256) sgemm_k(const float* __restrict__ X,
                                               const float* __restrict__ W,
                                               float* __restrict__ OUT) {
    constexpr int KD = (MODE == M_SH_GATE) ? 3 * Hd
                     : ((MODE == M_SH_DOWN || MODE == M_R_DOWN) ? Id : Hd);
    constexpr int ND = (MODE == M_SH_DOWN || MODE == M_R_DOWN) ? Hd : Id;
    constexpr int BM = 128, BN = 128, BK = 16;
    constexpr int PITCH = 132;

    int tileM = blockIdx.x;
    if constexpr (MODE >= M_R_GATE) {
        if (tileM >= g_ntiles) return;
    }
    int nb = blockIdx.y;
    int tid = threadIdx.x;

    __shared__ float sA[BK * PITCH];
    __shared__ float sB[BK * PITCH];

    // B base (per-expert slice for routed modes)
    const float* Bbase;
    if constexpr (MODE == M_SH_GATE) {
        Bbase = g_wp; (void)W;
    } else if constexpr (MODE == M_SH_UP || MODE == M_SH_DOWN) {
        Bbase = W;
    } else {
        int e = g_tile_expert[tileM];
        Bbase = W + (size_t)e * Hd * Id;
    }

    // per-thread A/B global pointers (2 float4 loads each)
    const float* aptr[2];
#pragma unroll
    for (int j = 0; j < 2; j++) {
        int f = tid + 256 * j;
        int r = f >> 2, c4 = f & 3;
        int row = tileM * BM + r;
        const float* p;
        if constexpr (MODE == M_SH_GATE) {
            int b = row >> 12, s = row & (Sq - 1);
            p = g_xpad + (size_t)(b * SP + s) * Hd;
        } else if constexpr (MODE == M_SH_UP) {
            p = X + (size_t)row * Hd;
        } else if constexpr (MODE == M_SH_DOWN) {
            p = g_shact + (size_t)row * Id;
        } else if constexpr (MODE == M_R_GATE || MODE == M_R_UP) {
            p = X + (size_t)g_as_tok[row] * Hd;
        } else {
            p = g_act + (size_t)row * Id;
        }
        aptr[j] = p + c4 * 4;
    }
    const float* bptr[2];
#pragma unroll
    for (int j = 0; j < 2; j++) {
        int f = tid + 256 * j;
        int br = f >> 5, bc4 = f & 31;
        bptr[j] = Bbase + (size_t)br * ND + nb * BN + bc4 * 4;
    }

    u64 acc[4][8];
#pragma unroll
    for (int i = 0; i < 4; i++)
#pragma unroll
        for (int j = 0; j < 8; j++) acc[i][j] = 0ull;  // (+0.f, +0.f)

    int ty = tid >> 4, tx = tid & 15;

    float4 rA[2], rB[2];
#pragma unroll
    for (int j = 0; j < 2; j++) {
        rA[j] = *(const float4*)(aptr[j]);
        rB[j] = *(const float4*)(bptr[j]);
    }

    for (int kt = 0; kt < KD; kt += BK) {
        __syncthreads();
#pragma unroll
        for (int j = 0; j < 2; j++) {
            int f = tid + 256 * j;
            int r = f >> 2, c4 = f & 3;
            sA[(c4 * 4 + 0) * PITCH + r] = rA[j].x;
            sA[(c4 * 4 + 1) * PITCH + r] = rA[j].y;
            sA[(c4 * 4 + 2) * PITCH + r] = rA[j].z;
            sA[(c4 * 4 + 3) * PITCH + r] = rA[j].w;
            int br = f >> 5, bc4 = f & 31;
            *(float4*)&sB[br * PITCH + bc4 * 4] = rB[j];
        }
        __syncthreads();
        if (kt + BK < KD) {
#pragma unroll
            for (int j = 0; j < 2; j++) {
                rA[j] = *(const float4*)(aptr[j] + (kt + BK));
                rB[j] = *(const float4*)(bptr[j] + (size_t)(kt + BK) * ND);
            }
        }
#pragma unroll
        for (int k = 0; k < BK; k++) {
            float4 a0 = *(const float4*)&sA[k * PITCH + ty * 8];
            float4 a1 = *(const float4*)&sA[k * PITCH + ty * 8 + 4];
            u64 A2[4];
            A2[0] = pack2(a0.x, a0.y);
            A2[1] = pack2(a0.z, a0.w);
            A2[2] = pack2(a1.x, a1.y);
            A2[3] = pack2(a1.z, a1.w);
            float4 b0 = *(const float4*)&sB[k * PITCH + tx * 8];
            float4 b1 = *(const float4*)&sB[k * PITCH + tx * 8 + 4];
            float bf[8] = {b0.x, b0.y, b0.z, b0.w, b1.x, b1.y, b1.z, b1.w};
#pragma unroll
            for (int j = 0; j < 8; j++) {
                u64 bb = pack2(bf[j], bf[j]);
#pragma unroll
                for (int i = 0; i < 4; i++) fma2(acc[i][j], A2[i], bb);
            }
        }
    }

    // ---------------- epilogue ----------------
    int row0 = tileM * BM + ty * 8;
    int col0 = nb * BN + tx * 8;
#pragma unroll
    for (int i2 = 0; i2 < 4; i2++) {
        float v[2][8];
#pragma unroll
        for (int j = 0; j < 8; j++) unpack2(acc[i2][j], v[0][j], v[1][j]);
#pragma unroll
        for (int h = 0; h < 2; h++) {
            int row = row0 + i2 * 2 + h;
            if constexpr (MODE == M_SH_GATE) {
                float* dst = g_shact + (size_t)row * Id + col0;
#pragma unroll
                for (int j = 0; j < 8; j++) dst[j] = v[h][j];
            } else if constexpr (MODE == M_SH_UP) {
                float* dst = g_shact + (size_t)row * Id + col0;
#pragma unroll
                for (int j = 0; j < 8; j++) {
                    float g = dst[j];
                    dst[j] = silu_f(g) * v[h][j];
                }
            } else if constexpr (MODE == M_SH_DOWN) {
                const float* xr = X + (size_t)row * Hd + col0;
                float w = g_wid[row];
                float* dst = OUT + (size_t)row * Hd + col0;
#pragma unroll
                for (int j = 0; j < 8; j++) dst[j] = v[h][j] + w * xr[j];
            } else if constexpr (MODE == M_R_GATE) {
                float* dst = g_act + (size_t)row * Id + col0;
#pragma unroll
                for (int j = 0; j < 8; j++) dst[j] = v[h][j];
            } else if constexpr (MODE == M_R_UP) {
                float* dst = g_act + (size_t)row * Id + col0;
#pragma unroll
                for (int j = 0; j < 8; j++) {
                    float g = dst[j];
                    dst[j] = silu_f(g) * v[h][j];
                }
            } else {  // M_R_DOWN
                float w = g_as_w[row];
                if (w != 0.f) {
                    int tok = g_as_tok[row];
                    float* dst = OUT + (size_t)tok * Hd + col0;
#pragma unroll
                    for (int j = 0; j < 8; j++) atomicAdd(dst + j, w * v[h][j]);
                }
            }
        }
    }
}

// ---------------- launch ----------------
extern "C" void kernel_launch(void* const* d_in, const int* in_sizes, int n_in,
                              void* d_out, int out_size) {
    (void)in_sizes; (void)n_in; (void)out_size;
    const float* x   = (const float*)d_in[0];  // hidden_states (B,S,H)
    const float* rw  = (const float*)d_in[1];  // router_w (H,E)
    const float* rb  = (const float*)d_in[2];  // router_bias (E)
    const float* gw  = (const float*)d_in[3];  // expert_gate_w (E-1,H,I)
    const float* uw  = (const float*)d_in[4];  // expert_up_w (E-1,H,I)
    const float* dw  = (const float*)d_in[5];  // expert_down_w (E-1,I,H)
    const float* cw  = (const float*)d_in[6];  // conv_w (I,H,KS)
    const float* suw = (const float*)d_in[7];  // shared_up_w (H,I)
    const float* sdw = (const float*)d_in[8];  // shared_down_w (I,H)
    float* out = (float*)d_out;

    zero_meta<<<1, 32>>>();
    router_kernel<<<Tn / 8, 256>>>(x, rw, rb);
    prefix_kernel<<<1, 32>>>();
    fill_assign<<<(MAXROWS + 255) / 256, 256>>>();
    assign_kernel<<<Tn / 256, 256>>>();
    build_xpad<<<(Bb * SP * Hd + 255) / 256, 256>>>(x);
    build_wp<<<(3 * Hd * Id + 255) / 256, 256>>>(cw);

    // shared expert: gate(conv as K=3072 GEMM) -> up(*silu gate) -> down(+identity)
    sgemm_k<M_SH_GATE><<<dim3(Tn / 128, Id / 128), 256>>>(x, nullptr, nullptr);
    sgemm_k<M_SH_UP><<<dim3(Tn / 128, Id / 128), 256>>>(x, suw, nullptr);
    sgemm_k<M_SH_DOWN><<<dim3(Tn / 128, Hd / 128), 256>>>(x, sdw, out);

    // routed experts on gathered, 128-aligned segments
    sgemm_k<M_R_GATE><<<dim3(MAX_TILES, Id / 128), 256>>>(x, gw, nullptr);
    sgemm_k<M_R_UP><<<dim3(MAX_TILES, Id / 128), 256>>>(x, uw, nullptr);
    sgemm_k<M_R_DOWN><<<dim3(MAX_TILES, Hd / 128), 256>>>(x, dw, out);
}

// round 6
// speedup vs baseline: 1.4886x; 1.4877x over previous
#include <cuda_runtime.h>
#include <cuda_bf16.h>
#include <math.h>
#include <stdint.h>

#define DINLINE __device__ __forceinline__

// ---------------- problem constants ----------------
constexpr int Bb = 4;
constexpr int Sq = 4096;
constexpr int Hd = 1024;
constexpr int Id = 512;
constexpr int NE = 15;                      // routed experts (idx 15 = identity)
constexpr int Tn = Bb * Sq;                 // 16384
constexpr int SP = Sq + 2;                  // left-padded seq (conv)
constexpr int MAXROWS = 2 * Tn + NE * 128;  // 34688
constexpr int MAX_TILES = MAXROWS / 128;    // 271

// triplet-expanded K sizes
constexpr int K3H = 3 * Hd;    // 3072
constexpr int K3I = 3 * Id;    // 1536
constexpr int K3C = 9 * Hd;    // 9216 (conv: 3 shifts x 3072)

// ---------------- device scratch ----------------
__device__ __align__(16) __nv_bfloat16 g_x3[(size_t)Bb * SP * K3H];     // padded x, triplet
__device__ __align__(16) __nv_bfloat16 g_gx3[(size_t)MAXROWS * K3H];    // gathered routed x
__device__ __align__(16) __nv_bfloat16 g_shact3[(size_t)Tn * K3I];      // shared silu*up
__device__ __align__(16) __nv_bfloat16 g_act3[(size_t)MAXROWS * K3I];   // routed silu*up
__device__ __align__(16) float         g_shact[(size_t)Tn * Id];        // shared conv gate fp32
__device__ __align__(16) __nv_bfloat16 g_wp3T[(size_t)Id * K3C];        // conv W, B-layout
__device__ __align__(16) __nv_bfloat16 g_su3T[(size_t)Id * K3H];
__device__ __align__(16) __nv_bfloat16 g_sd3T[(size_t)Hd * K3I];
__device__ __align__(16) __nv_bfloat16 g_guT[(size_t)NE * 1024 * K3H];  // interleaved gate/up
__device__ __align__(16) __nv_bfloat16 g_dw3T[(size_t)NE * Hd * K3I];

__device__ int   g_top_idx[Tn * 2];
__device__ float g_top_w[Tn * 2];
__device__ float g_wid[Tn];
__device__ int   g_counts[NE];
__device__ int   g_cursor[NE];
__device__ int   g_off[NE + 1];
__device__ int   g_tile_expert[MAX_TILES];
__device__ int   g_ntiles;
__device__ int   g_as_tok[MAXROWS];
__device__ float g_as_w[MAXROWS];

// ---------------- helpers ----------------
DINLINE float silu_f(float g) { return g / (1.f + expf(-g)); }
DINLINE void splitf(float v, __nv_bfloat16& h, __nv_bfloat16& l) {
    h = __float2bfloat16(v);
    l = __float2bfloat16(v - __bfloat162float(h));
}
DINLINE unsigned pkbf(__nv_bfloat16 a, __nv_bfloat16 b) {
    unsigned short ua = *(unsigned short*)&a, ub = *(unsigned short*)&b;
    return (unsigned)ua | ((unsigned)ub << 16);
}

DINLINE unsigned smem_u32(const void* p) {
    unsigned a;
    asm("{ .reg .u64 t; cvta.to.shared.u64 t, %1; cvt.u32.u64 %0, t; }" : "=r"(a) : "l"(p));
    return a;
}
DINLINE void cpa16(unsigned d, const void* g) {
    asm volatile("cp.async.cg.shared.global [%0], [%1], 16;" :: "r"(d), "l"(g) : "memory");
}
DINLINE void ldsm4(unsigned* r, unsigned a) {
    asm volatile("ldmatrix.sync.aligned.m8n8.x4.shared.b16 {%0,%1,%2,%3}, [%4];"
        : "=r"(r[0]), "=r"(r[1]), "=r"(r[2]), "=r"(r[3]) : "r"(a));
}
DINLINE void mma16816(float* c, const unsigned* a, unsigned b0, unsigned b1) {
    asm volatile(
        "mma.sync.aligned.m16n8k16.row.col.f32.bf16.bf16.f32 "
        "{%0,%1,%2,%3}, {%4,%5,%6,%7}, {%8,%9}, {%0,%1,%2,%3};"
        : "+f"(c[0]), "+f"(c[1]), "+f"(c[2]), "+f"(c[3])
        : "r"(a[0]), "r"(a[1]), "r"(a[2]), "r"(a[3]), "r"(b0), "r"(b1));
}

// ---------------- routing kernels ----------------
__global__ void zero_meta() {
    int t = threadIdx.x;
    if (t < NE) { g_counts[t] = 0; g_cursor[t] = 0; }
}

__global__ void router_kernel(const float* __restrict__ x,
                              const float* __restrict__ rw,
                              const float* __restrict__ rb) {
    int gw = (blockIdx.x * blockDim.x + threadIdx.x) >> 5;
    int lane = threadIdx.x & 31;
    if (gw >= Tn) return;
    const float* xr = x + (size_t)gw * Hd;
    float acc[16];
#pragma unroll
    for (int e = 0; e < 16; e++) acc[e] = 0.f;
    for (int h = lane; h < Hd; h += 32) {
        float xv = xr[h];
        const float4* w4 = (const float4*)(rw + (size_t)h * 16);
        float4 w0 = w4[0], w1 = w4[1], w2 = w4[2], w3 = w4[3];
        acc[0] += xv*w0.x;  acc[1] += xv*w0.y;  acc[2] += xv*w0.z;  acc[3] += xv*w0.w;
        acc[4] += xv*w1.x;  acc[5] += xv*w1.y;  acc[6] += xv*w1.z;  acc[7] += xv*w1.w;
        acc[8] += xv*w2.x;  acc[9] += xv*w2.y;  acc[10]+= xv*w2.z;  acc[11]+= xv*w2.w;
        acc[12]+= xv*w3.x;  acc[13]+= xv*w3.y;  acc[14]+= xv*w3.z;  acc[15]+= xv*w3.w;
    }
#pragma unroll
    for (int e = 0; e < 16; e++) {
#pragma unroll
        for (int o = 16; o > 0; o >>= 1) acc[e] += __shfl_xor_sync(0xffffffffu, acc[e], o);
    }
    if (lane == 0) {
        float l[16]; float m = -1e30f;
#pragma unroll
        for (int e = 0; e < 16; e++) { l[e] = acc[e] + rb[e]; m = fmaxf(m, l[e]); }
        float p[16]; float s = 0.f;
#pragma unroll
        for (int e = 0; e < 16; e++) { p[e] = expf(l[e] - m); s += p[e]; }
        int i1 = 0; float p1 = p[0];
#pragma unroll
        for (int e = 1; e < 16; e++) if (p[e] > p1) { p1 = p[e]; i1 = e; }
        int i2 = -1; float p2 = -1e30f;
#pragma unroll
        for (int e = 0; e < 16; e++) if (e != i1 && p[e] > p2) { p2 = p[e]; i2 = e; }
        float pr1 = p1 / s, pr2 = p2 / s;
        float d = pr1 + pr2 + 1e-6f;
        float w1 = pr1 / d, w2 = pr2 / d;
        g_top_idx[gw*2] = i1; g_top_idx[gw*2+1] = i2;
        g_top_w[gw*2] = w1;   g_top_w[gw*2+1] = w2;
        float wid = 0.f;
        if (i1 == NE) wid = w1; else if (i2 == NE) wid = w2;
        g_wid[gw] = wid;
        if (i1 < NE) atomicAdd(&g_counts[i1], 1);
        if (i2 < NE) atomicAdd(&g_counts[i2], 1);
    }
}

__global__ void prefix_kernel() {
    if (threadIdx.x == 0 && blockIdx.x == 0) {
        int off = 0;
        for (int e = 0; e < NE; e++) {
            g_off[e] = off;
            int a = (g_counts[e] + 127) & ~127;
            for (int t = off >> 7; t < (off + a) >> 7; t++) g_tile_expert[t] = e;
            off += a;
        }
        g_off[NE] = off;
        g_ntiles = off >> 7;
    }
}

__global__ void fill_assign() {
    int i = blockIdx.x * blockDim.x + threadIdx.x;
    if (i < MAXROWS) { g_as_tok[i] = 0; g_as_w[i] = 0.f; }
}

__global__ void assign_kernel() {
    int t = blockIdx.x * blockDim.x + threadIdx.x;
    if (t >= Tn) return;
#pragma unroll
    for (int k = 0; k < 2; k++) {
        int e = g_top_idx[t*2 + k];
        if (e < NE) {
            int p = atomicAdd(&g_cursor[e], 1);
            int r = g_off[e] + p;
            g_as_tok[r] = t;
            g_as_w[r] = g_top_w[t*2 + k];
        }
    }
}

// ---------------- triplet expansion kernels ----------------
// A-pattern triplet: (h, l, h).  B-pattern triplet: (h, h, l).

// g_x3[rj][3h..] = tripletA(x[b][rj%SP - 2][h]), zeros for first 2 rows
__global__ void expand_x3(const float* __restrict__ x) {
    size_t i = (size_t)blockIdx.x * 256 + threadIdx.x;
    if (i >= (size_t)Bb * SP * Hd / 2) return;
    size_t e = i * 2;
    int h = (int)(e & 1023);
    int rj = (int)(e >> 10);
    int r = rj % SP, b = rj / SP;
    float2 v = make_float2(0.f, 0.f);
    if (r >= 2) v = *(const float2*)(x + (((size_t)(b * Sq + r - 2)) << 10) + h);
    __nv_bfloat16 h0,l0,h1,l1; splitf(v.x,h0,l0); splitf(v.y,h1,l1);
    unsigned* p = (unsigned*)(g_x3 + (size_t)rj * K3H + 3*h);
    p[0] = pkbf(h0,l0); p[1] = pkbf(h0,h1); p[2] = pkbf(l1,h1);
}

// g_gx3[r][3h..] = tripletA(x[as_tok[r]][h])
__global__ void gather_gx3(const float* __restrict__ x) {
    size_t i = (size_t)blockIdx.x * 256 + threadIdx.x;
    if (i >= (size_t)MAXROWS * Hd / 2) return;
    size_t e = i * 2;
    int h = (int)(e & 1023);
    int r = (int)(e >> 10);
    int tok = g_as_tok[r];
    float2 v = *(const float2*)(x + (((size_t)tok) << 10) + h);
    __nv_bfloat16 h0,l0,h1,l1; splitf(v.x,h0,l0); splitf(v.y,h1,l1);
    unsigned* p = (unsigned*)(g_gx3 + (size_t)r * K3H + 3*h);
    p[0] = pkbf(h0,l0); p[1] = pkbf(h0,h1); p[2] = pkbf(l1,h1);
}

// conv W: wp3T[i][kk*3072 + 3h..] = tripletB(cw[i][h][kk])
__global__ void build_wp3T(const float* __restrict__ cw) {
    int idx = blockIdx.x * 256 + threadIdx.x;
    if (idx >= Id * Hd * 3) return;
    int kk = idx % 3, hh = (idx / 3) & 1023, ii = idx / 3072;
    float w = cw[(size_t)ii * 3072 + hh * 3 + kk];
    __nv_bfloat16 h_, l_; splitf(w, h_, l_);
    __nv_bfloat16* q = g_wp3T + (size_t)ii * K3C + kk * K3H + 3*hh;
    q[0] = h_; q[1] = h_; q[2] = l_;
}

// su3T[i][3h..] = tripletB(suw[h][i])
__global__ void build_su3T(const float* __restrict__ suw) {
    int idx = blockIdx.x * 256 + threadIdx.x;
    if (idx >= Hd * Id) return;
    int i = idx & 511, h = idx >> 9;
    float w = suw[(size_t)h * Id + i];
    __nv_bfloat16 h_, l_; splitf(w, h_, l_);
    __nv_bfloat16* q = g_su3T + (size_t)i * K3H + 3*h;
    q[0] = h_; q[1] = h_; q[2] = l_;
}

// sd3T[h][3i..] = tripletB(sdw[i][h])
__global__ void build_sd3T(const float* __restrict__ sdw) {
    int idx = blockIdx.x * 256 + threadIdx.x;
    if (idx >= Id * Hd) return;
    int h = idx & 1023, i = idx >> 10;
    float w = sdw[(size_t)i * Hd + h];
    __nv_bfloat16 h_, l_; splitf(w, h_, l_);
    __nv_bfloat16* q = g_sd3T + (size_t)h * K3I + 3*i;
    q[0] = h_; q[1] = h_; q[2] = l_;
}

// guT[e][2i+p][3h..] = tripletB( (p? uw : gw)[e][h][i] )
__global__ void build_guT(const float* __restrict__ gw, const float* __restrict__ uw) {
    size_t idx = (size_t)blockIdx.x * 256 + threadIdx.x;
    if (idx >= (size_t)NE * Hd * Id * 2) return;
    int p = (int)(idx & 1);
    int i = (int)((idx >> 1) & 511);
    int h = (int)((idx >> 10) & 1023);
    int e = (int)(idx >> 20);
    const float* src = p ? uw : gw;
    float w = src[(((size_t)e << 10) + h) * Id + i];
    __nv_bfloat16 h_, l_; splitf(w, h_, l_);
    __nv_bfloat16* q = g_guT + ((size_t)e * 1024 + 2*i + p) * K3H + 3*h;
    q[0] = h_; q[1] = h_; q[2] = l_;
}

// dw3T[e][h][3i..] = tripletB(dw[e][i][h])
__global__ void build_dw3T(const float* __restrict__ dw) {
    size_t idx = (size_t)blockIdx.x * 256 + threadIdx.x;
    if (idx >= (size_t)NE * Id * Hd) return;
    int h = (int)(idx & 1023);
    int i = (int)((idx >> 10) & 511);
    int e = (int)(idx >> 19);
    float w = dw[(((size_t)e << 9) + i) * Hd + h];
    __nv_bfloat16 h_, l_; splitf(w, h_, l_);
    __nv_bfloat16* q = g_dw3T + ((size_t)e * Hd + h) * K3I + 3*i;
    q[0] = h_; q[1] = h_; q[2] = l_;
}

// ---------------- mma.sync GEMM ----------------
enum { M_SH_GATE = 0, M_SH_UP, M_SH_DOWN, M_R_GU, M_R_DOWN };

template <int MODE>
__global__ void __launch_bounds__(256) mmak(const float* __restrict__ X,
                                            float* __restrict__ OUT) {
    constexpr int K3 = (MODE == M_SH_GATE) ? K3C
                     : (MODE == M_SH_UP || MODE == M_R_GU) ? K3H : K3I;
    constexpr int NK = K3 / 32;
    constexpr int BROWS = (MODE == M_R_GU || MODE == M_R_DOWN) ? 1024 : 0;

    int tileM = blockIdx.x, nb = blockIdx.y;
    if constexpr (MODE == M_R_GU || MODE == M_R_DOWN) {
        if (tileM >= g_ntiles) return;
    }

    __shared__ __align__(16) char smem[3 * 16384];
    unsigned smbase = smem_u32(smem);

    int tid = threadIdx.x;
    int warp = tid >> 5, lane = tid & 31;
    int wm = warp & 3, wn = warp >> 2;

    // B base (expert slice for routed)
    const __nv_bfloat16* Bb_;
    if constexpr (MODE == M_SH_GATE)      Bb_ = g_wp3T;
    else if constexpr (MODE == M_SH_UP)   Bb_ = g_su3T;
    else if constexpr (MODE == M_SH_DOWN) Bb_ = g_sd3T;
    else if constexpr (MODE == M_R_GU)    Bb_ = g_guT  + (size_t)g_tile_expert[tileM] * BROWS * K3;
    else                                  Bb_ = g_dw3T + (size_t)g_tile_expert[tileM] * BROWS * K3;

    // per-thread load slots: 2 A chunks + 2 B chunks of 16B
    int rA[2], cA[2], jrow[2];
    const __nv_bfloat16* pA[2];
    const __nv_bfloat16* pB[2];
    unsigned oA[2], oB[2];
#pragma unroll
    for (int t = 0; t < 2; t++) {
        int id = tid + 256 * t;
        int r = id >> 2, c = id & 3;
        rA[t] = r; cA[t] = c;
        int rowg = tileM * 128 + r;
        if constexpr (MODE == M_SH_GATE || MODE == M_SH_UP) {
            int b = rowg >> 12, s = rowg & 4095;
            jrow[t] = b * SP + s;
            pA[t] = g_x3 + ((size_t)(jrow[t] + 2)) * K3H + c * 8;  // used by SH_UP only
        } else if constexpr (MODE == M_R_GU) {
            pA[t] = g_gx3 + (size_t)rowg * K3H + c * 8;
        } else if constexpr (MODE == M_SH_DOWN) {
            pA[t] = g_shact3 + (size_t)rowg * K3I + c * 8;
        } else {
            pA[t] = g_act3 + (size_t)rowg * K3I + c * 8;
        }
        pB[t] = Bb_ + (size_t)(nb * 128 + r) * K3 + c * 8;
        unsigned sw = (unsigned)(c ^ ((r >> 1) & 3));
        oA[t] = (unsigned)(r * 64) + (sw << 4);
        oB[t] = 8192u + (unsigned)(r * 64) + (sw << 4);
    }

    auto ldst = [&](int kt, int st) {
        unsigned sb = smbase + st * 16384;
#pragma unroll
        for (int t = 0; t < 2; t++) {
            const __nv_bfloat16* ga;
            if constexpr (MODE == M_SH_GATE) {
                int ko = kt * 32 + cA[t] * 8;
                int sh = (ko >= 2 * K3H) ? 2 : (ko >= K3H ? 1 : 0);
                ga = g_x3 + (size_t)(jrow[t] + sh) * K3H + (ko - sh * K3H);
            } else {
                ga = pA[t] + kt * 32;
            }
            cpa16(sb + oA[t], ga);
            cpa16(sb + oB[t], pB[t] + kt * 32);
        }
        asm volatile("cp.async.commit_group;" ::: "memory");
    };

    float acc[2][8][4];
#pragma unroll
    for (int a = 0; a < 2; a++)
#pragma unroll
        for (int b = 0; b < 8; b++)
#pragma unroll
            for (int c = 0; c < 4; c++) acc[a][b][c] = 0.f;

    ldst(0, 0);
    ldst(1, 1);

    int idx = lane >> 3;
    int rr = (lane & 7) + 8 * (idx & 1);
    int kb = idx >> 1;

    for (int kt = 0; kt < NK; kt++) {
        int st = kt % 3;
        if (kt + 1 < NK) { asm volatile("cp.async.wait_group 1;" ::: "memory"); }
        else             { asm volatile("cp.async.wait_group 0;" ::: "memory"); }
        __syncthreads();
        if (kt + 2 < NK) ldst(kt + 2, (kt + 2) % 3);

        unsigned sA = smbase + st * 16384, sB = sA + 8192;
#pragma unroll
        for (int kc = 0; kc < 2; kc++) {
            int kch = kc * 2 + kb;
            unsigned af[2][4], bfr[4][4];
#pragma unroll
            for (int mt = 0; mt < 2; mt++) {
                int r = wm * 32 + mt * 16 + rr;
                ldsm4(af[mt], sA + r * 64 + ((unsigned)(kch ^ ((r >> 1) & 3)) << 4));
            }
#pragma unroll
            for (int nt2 = 0; nt2 < 4; nt2++) {
                int rn = wn * 64 + nt2 * 16 + rr;
                ldsm4(bfr[nt2], sB + rn * 64 + ((unsigned)(kch ^ ((rn >> 1) & 3)) << 4));
            }
#pragma unroll
            for (int mt = 0; mt < 2; mt++)
#pragma unroll
                for (int nt = 0; nt < 8; nt++)
                    mma16816(acc[mt][nt], af[mt], bfr[nt >> 1][nt & 1], bfr[nt >> 1][2 + (nt & 1)]);
        }
    }

    // ---------------- epilogue ----------------
    int l2 = lane >> 2, l4 = lane & 3;
#pragma unroll
    for (int mt = 0; mt < 2; mt++) {
#pragma unroll
        for (int hh = 0; hh < 2; hh++) {
            int rowg = tileM * 128 + wm * 32 + mt * 16 + l2 + 8 * hh;
            if constexpr (MODE == M_R_DOWN) {
                float w = g_as_w[rowg];
                if (w != 0.f) {
                    int tok = g_as_tok[rowg];
                    float* dst = OUT + (size_t)tok * Hd;
#pragma unroll
                    for (int nt = 0; nt < 8; nt++) {
                        int colg = nb * 128 + wn * 64 + nt * 8 + l4 * 2;
                        atomicAdd(dst + colg,     w * acc[mt][nt][2*hh]);
                        atomicAdd(dst + colg + 1, w * acc[mt][nt][2*hh + 1]);
                    }
                }
            } else if constexpr (MODE == M_SH_DOWN) {
                float w = g_wid[rowg];
                const float* xr = X + (size_t)rowg * Hd;
                float* dst = OUT + (size_t)rowg * Hd;
#pragma unroll
                for (int nt = 0; nt < 8; nt++) {
                    int colg = nb * 128 + wn * 64 + nt * 8 + l4 * 2;
                    float2 xv = *(const float2*)(xr + colg);
                    float2 o;
                    o.x = acc[mt][nt][2*hh]     + w * xv.x;
                    o.y = acc[mt][nt][2*hh + 1] + w * xv.y;
                    *(float2*)(dst + colg) = o;
                }
            } else if constexpr (MODE == M_SH_GATE) {
                float* dst = g_shact + (size_t)rowg * Id;
#pragma unroll
                for (int nt = 0; nt < 8; nt++) {
                    int colg = nb * 128 + wn * 64 + nt * 8 + l4 * 2;
                    *(float2*)(dst + colg) =
                        make_float2(acc[mt][nt][2*hh], acc[mt][nt][2*hh + 1]);
                }
            } else if constexpr (MODE == M_SH_UP) {
                const float* gs = g_shact + (size_t)rowg * Id;
                __nv_bfloat16* d3 = g_shact3 + (size_t)rowg * K3I;
#pragma unroll
                for (int nt = 0; nt < 8; nt++) {
                    int colg = nb * 128 + wn * 64 + nt * 8 + l4 * 2;
                    float2 g = *(const float2*)(gs + colg);
                    float v0 = silu_f(g.x) * acc[mt][nt][2*hh];
                    float v1 = silu_f(g.y) * acc[mt][nt][2*hh + 1];
                    __nv_bfloat16 h0,l0,h1,l1; splitf(v0,h0,l0); splitf(v1,h1,l1);
                    unsigned* p = (unsigned*)(d3 + 3 * colg);
                    p[0] = pkbf(h0,l0); p[1] = pkbf(h0,h1); p[2] = pkbf(l1,h1);
                }
            } else {  // M_R_GU: interleaved (gate, up) column pairs
                __nv_bfloat16* d3 = g_act3 + (size_t)rowg * K3I;
#pragma unroll
                for (int nt = 0; nt < 8; nt++) {
                    int i = nb * 64 + wn * 32 + nt * 4 + l4;   // value column
                    float v = silu_f(acc[mt][nt][2*hh]) * acc[mt][nt][2*hh + 1];
                    __nv_bfloat16 h_, l_; splitf(v, h_, l_);
                    __nv_bfloat16* p = d3 + 3 * i;
                    p[0] = h_; p[1] = l_; p[2] = h_;
                }
            }
        }
    }
}

// ---------------- launch ----------------
extern "C" void kernel_launch(void* const* d_in, const int* in_sizes, int n_in,
                              void* d_out, int out_size) {
    (void)in_sizes; (void)n_in; (void)out_size;
    const float* x   = (const float*)d_in[0];
    const float* rw  = (const float*)d_in[1];
    const float* rb  = (const float*)d_in[2];
    const float* gw  = (const float*)d_in[3];
    const float* uw  = (const float*)d_in[4];
    const float* dw  = (const float*)d_in[5];
    const float* cw  = (const float*)d_in[6];
    const float* suw = (const float*)d_in[7];
    const float* sdw = (const float*)d_in[8];
    float* out = (float*)d_out;

    // routing
    zero_meta<<<1, 32>>>();
    router_kernel<<<Tn / 8, 256>>>(x, rw, rb);
    prefix_kernel<<<1, 32>>>();
    fill_assign<<<(MAXROWS + 255) / 256, 256>>>();
    assign_kernel<<<Tn / 256, 256>>>();

    // triplet expansions
    {
        size_t n;
        n = (size_t)Bb * SP * Hd / 2;   expand_x3 <<<(unsigned)((n + 255) / 256), 256>>>(x);
        n = (size_t)MAXROWS * Hd / 2;   gather_gx3<<<(unsigned)((n + 255) / 256), 256>>>(x);
        n = (size_t)Id * Hd * 3;        build_wp3T<<<(unsigned)((n + 255) / 256), 256>>>(cw);
        n = (size_t)Hd * Id;            build_su3T<<<(unsigned)((n + 255) / 256), 256>>>(suw);
        n = (size_t)Id * Hd;            build_sd3T<<<(unsigned)((n + 255) / 256), 256>>>(sdw);
        n = (size_t)NE * Hd * Id * 2;   build_guT <<<(unsigned)((n + 255) / 256), 256>>>(gw, uw);
        n = (size_t)NE * Id * Hd;       build_dw3T<<<(unsigned)((n + 255) / 256), 256>>>(dw);
    }

    // shared expert: conv-gate -> up(*silu) -> down(+identity expert)
    mmak<M_SH_GATE><<<dim3(Tn / 128, Id / 128), 256>>>(x, out);
    mmak<M_SH_UP>  <<<dim3(Tn / 128, Id / 128), 256>>>(x, out);
    mmak<M_SH_DOWN><<<dim3(Tn / 128, Hd / 128), 256>>>(x, out);

    // routed experts: fused gate+up (interleaved cols), then weighted scatter down
    mmak<M_R_GU>   <<<dim3(MAX_TILES, 1024 / 128), 256>>>(x, out);
    mmak<M_R_DOWN> <<<dim3(MAX_TILES, Hd / 128), 256>>>(x, out);
}

// round 7
// speedup vs baseline: 1.6173x; 1.0865x over previous
#include <cuda_runtime.h>
#include <cuda_bf16.h>
#include <math.h>
#include <stdint.h>

#define DINLINE __device__ __forceinline__

// ---------------- problem constants ----------------
constexpr int Bb = 4;
constexpr int Sq = 4096;
constexpr int Hd = 1024;
constexpr int Id = 512;
constexpr int NE = 15;                      // routed experts (idx 15 = identity)
constexpr int Tn = Bb * Sq;                 // 16384
constexpr int SP = Sq + 2;                  // left-padded seq (conv)
constexpr int MAXROWS = 2 * Tn + NE * 128;  // 34688
constexpr int MAX_TILES = MAXROWS / 128;    // 271

// triplet-expanded K sizes
constexpr int K3H = 3 * Hd;    // 3072
constexpr int K3I = 3 * Id;    // 1536
constexpr int K3C = 9 * Hd;    // 9216 (conv: 3 shifts x 3072)

// ---------------- device scratch ----------------
__device__ __align__(16) __nv_bfloat16 g_x3[(size_t)Bb * SP * K3H];     // padded x, triplet
__device__ __align__(16) __nv_bfloat16 g_shact3[(size_t)Tn * K3I];      // shared silu*up
__device__ __align__(16) __nv_bfloat16 g_act3[(size_t)MAXROWS * K3I];   // routed silu*up
__device__ __align__(16) float         g_shact[(size_t)Tn * Id];        // shared conv gate fp32
__device__ __align__(16) __nv_bfloat16 g_wp3T[(size_t)Id * K3C];        // conv W, B-layout
__device__ __align__(16) __nv_bfloat16 g_su3T[(size_t)Id * K3H];
__device__ __align__(16) __nv_bfloat16 g_sd3T[(size_t)Hd * K3I];
__device__ __align__(16) __nv_bfloat16 g_guT[(size_t)NE * 1024 * K3H];  // interleaved gate/up
__device__ __align__(16) __nv_bfloat16 g_dw3T[(size_t)NE * Hd * K3I];

__device__ int   g_top_idx[Tn * 2];
__device__ float g_top_w[Tn * 2];
__device__ float g_wid[Tn];
__device__ int   g_counts[NE];
__device__ int   g_cursor[NE];
__device__ int   g_off[NE + 1];
__device__ int   g_tile_expert[MAX_TILES];
__device__ int   g_ntiles;
__device__ int   g_as_tok[MAXROWS];
__device__ float g_as_w[MAXROWS];

// ---------------- helpers ----------------
DINLINE float silu_f(float g) { return g / (1.f + expf(-g)); }
DINLINE void splitf(float v, __nv_bfloat16& h, __nv_bfloat16& l) {
    h = __float2bfloat16(v);
    l = __float2bfloat16(v - __bfloat162float(h));
}
DINLINE unsigned pkbf(__nv_bfloat16 a, __nv_bfloat16 b) {
    unsigned short ua = *(unsigned short*)&a, ub = *(unsigned short*)&b;
    return (unsigned)ua | ((unsigned)ub << 16);
}

DINLINE unsigned smem_u32(const void* p) {
    unsigned a;
    asm("{ .reg .u64 t; cvta.to.shared.u64 t, %1; cvt.u32.u64 %0, t; }" : "=r"(a) : "l"(p));
    return a;
}
DINLINE void cpa16(unsigned d, const void* g) {
    asm volatile("cp.async.cg.shared.global [%0], [%1], 16;" :: "r"(d), "l"(g) : "memory");
}
DINLINE void ldsm4(unsigned* r, unsigned a) {
    asm volatile("ldmatrix.sync.aligned.m8n8.x4.shared.b16 {%0,%1,%2,%3}, [%4];"
        : "=r"(r[0]), "=r"(r[1]), "=r"(r[2]), "=r"(r[3]) : "r"(a));
}
DINLINE void mma16816(float* c, const unsigned* a, unsigned b0, unsigned b1) {
    asm volatile(
        "mma.sync.aligned.m16n8k16.row.col.f32.bf16.bf16.f32 "
        "{%0,%1,%2,%3}, {%4,%5,%6,%7}, {%8,%9}, {%0,%1,%2,%3};"
        : "+f"(c[0]), "+f"(c[1]), "+f"(c[2]), "+f"(c[3])
        : "r"(a[0]), "r"(a[1]), "r"(a[2]), "r"(a[3]), "r"(b0), "r"(b1));
}

// ---------------- routing kernels ----------------
__global__ void zero_meta() {
    int t = threadIdx.x;
    if (t < NE) { g_counts[t] = 0; g_cursor[t] = 0; }
}

__global__ void router_kernel(const float* __restrict__ x,
                              const float* __restrict__ rw,
                              const float* __restrict__ rb) {
    int gw = (blockIdx.x * blockDim.x + threadIdx.x) >> 5;
    int lane = threadIdx.x & 31;
    if (gw >= Tn) return;
    const float* xr = x + (size_t)gw * Hd;
    float acc[16];
#pragma unroll
    for (int e = 0; e < 16; e++) acc[e] = 0.f;
    for (int h = lane; h < Hd; h += 32) {
        float xv = xr[h];
        const float4* w4 = (const float4*)(rw + (size_t)h * 16);
        float4 w0 = w4[0], w1 = w4[1], w2 = w4[2], w3 = w4[3];
        acc[0] += xv*w0.x;  acc[1] += xv*w0.y;  acc[2] += xv*w0.z;  acc[3] += xv*w0.w;
        acc[4] += xv*w1.x;  acc[5] += xv*w1.y;  acc[6] += xv*w1.z;  acc[7] += xv*w1.w;
        acc[8] += xv*w2.x;  acc[9] += xv*w2.y;  acc[10]+= xv*w2.z;  acc[11]+= xv*w2.w;
        acc[12]+= xv*w3.x;  acc[13]+= xv*w3.y;  acc[14]+= xv*w3.z;  acc[15]+= xv*w3.w;
    }
#pragma unroll
    for (int e = 0; e < 16; e++) {
#pragma unroll
        for (int o = 16; o > 0; o >>= 1) acc[e] += __shfl_xor_sync(0xffffffffu, acc[e], o);
    }
    if (lane == 0) {
        float l[16]; float m = -1e30f;
#pragma unroll
        for (int e = 0; e < 16; e++) { l[e] = acc[e] + rb[e]; m = fmaxf(m, l[e]); }
        float p[16]; float s = 0.f;
#pragma unroll
        for (int e = 0; e < 16; e++) { p[e] = expf(l[e] - m); s += p[e]; }
        int i1 = 0; float p1 = p[0];
#pragma unroll
        for (int e = 1; e < 16; e++) if (p[e] > p1) { p1 = p[e]; i1 = e; }
        int i2 = -1; float p2 = -1e30f;
#pragma unroll
        for (int e = 0; e < 16; e++) if (e != i1 && p[e] > p2) { p2 = p[e]; i2 = e; }
        float pr1 = p1 / s, pr2 = p2 / s;
        float d = pr1 + pr2 + 1e-6f;
        float w1 = pr1 / d, w2 = pr2 / d;
        g_top_idx[gw*2] = i1; g_top_idx[gw*2+1] = i2;
        g_top_w[gw*2] = w1;   g_top_w[gw*2+1] = w2;
        float wid = 0.f;
        if (i1 == NE) wid = w1; else if (i2 == NE) wid = w2;
        g_wid[gw] = wid;
        if (i1 < NE) atomicAdd(&g_counts[i1], 1);
        if (i2 < NE) atomicAdd(&g_counts[i2], 1);
    }
}

__global__ void prefix_kernel() {
    if (threadIdx.x == 0 && blockIdx.x == 0) {
        int off = 0;
        for (int e = 0; e < NE; e++) {
            g_off[e] = off;
            int a = (g_counts[e] + 127) & ~127;
            for (int t = off >> 7; t < (off + a) >> 7; t++) g_tile_expert[t] = e;
            off += a;
        }
        g_off[NE] = off;
        g_ntiles = off >> 7;
    }
}

__global__ void fill_assign() {
    int i = blockIdx.x * blockDim.x + threadIdx.x;
    if (i < MAXROWS) { g_as_tok[i] = 0; g_as_w[i] = 0.f; }
}

__global__ void assign_kernel() {
    int t = blockIdx.x * blockDim.x + threadIdx.x;
    if (t >= Tn) return;
#pragma unroll
    for (int k = 0; k < 2; k++) {
        int e = g_top_idx[t*2 + k];
        if (e < NE) {
            int p = atomicAdd(&g_cursor[e], 1);
            int r = g_off[e] + p;
            g_as_tok[r] = t;
            g_as_w[r] = g_top_w[t*2 + k];
        }
    }
}

// ---------------- triplet expansion kernels ----------------
// A-pattern triplet: (h, l, h).  B-pattern triplet: (h, h, l).

// g_x3[rj][3h..] = tripletA(x[b][rj%SP - 2][h]), zeros for first 2 rows
__global__ void expand_x3(const float* __restrict__ x) {
    size_t i = (size_t)blockIdx.x * 256 + threadIdx.x;
    if (i >= (size_t)Bb * SP * Hd / 2) return;
    size_t e = i * 2;
    int h = (int)(e & 1023);
    int rj = (int)(e >> 10);
    int r = rj % SP, b = rj / SP;
    float2 v = make_float2(0.f, 0.f);
    if (r >= 2) v = *(const float2*)(x + (((size_t)(b * Sq + r - 2)) << 10) + h);
    __nv_bfloat16 h0,l0,h1,l1; splitf(v.x,h0,l0); splitf(v.y,h1,l1);
    unsigned* p = (unsigned*)(g_x3 + (size_t)rj * K3H + 3*h);
    p[0] = pkbf(h0,l0); p[1] = pkbf(h0,h1); p[2] = pkbf(l1,h1);
}

// conv W: wp3T[i][kk*3072 + 3h..] = tripletB(cw[i][h][kk])
__global__ void build_wp3T(const float* __restrict__ cw) {
    int idx = blockIdx.x * 256 + threadIdx.x;
    if (idx >= Id * Hd * 3) return;
    int kk = idx % 3, hh = (idx / 3) & 1023, ii = idx / 3072;
    float w = cw[(size_t)ii * 3072 + hh * 3 + kk];
    __nv_bfloat16 h_, l_; splitf(w, h_, l_);
    __nv_bfloat16* q = g_wp3T + (size_t)ii * K3C + kk * K3H + 3*hh;
    q[0] = h_; q[1] = h_; q[2] = l_;
}

// su3T[i][3h..] = tripletB(suw[h][i])
__global__ void build_su3T(const float* __restrict__ suw) {
    int idx = blockIdx.x * 256 + threadIdx.x;
    if (idx >= Hd * Id) return;
    int i = idx & 511, h = idx >> 9;
    float w = suw[(size_t)h * Id + i];
    __nv_bfloat16 h_, l_; splitf(w, h_, l_);
    __nv_bfloat16* q = g_su3T + (size_t)i * K3H + 3*h;
    q[0] = h_; q[1] = h_; q[2] = l_;
}

// sd3T[h][3i..] = tripletB(sdw[i][h])
__global__ void build_sd3T(const float* __restrict__ sdw) {
    int idx = blockIdx.x * 256 + threadIdx.x;
    if (idx >= Id * Hd) return;
    int h = idx & 1023, i = idx >> 10;
    float w = sdw[(size_t)i * Hd + h];
    __nv_bfloat16 h_, l_; splitf(w, h_, l_);
    __nv_bfloat16* q = g_sd3T + (size_t)h * K3I + 3*i;
    q[0] = h_; q[1] = h_; q[2] = l_;
}

// guT[e][2i+p][3h..] = tripletB( (p? uw : gw)[e][h][i] )
__global__ void build_guT(const float* __restrict__ gw, const float* __restrict__ uw) {
    size_t idx = (size_t)blockIdx.x * 256 + threadIdx.x;
    if (idx >= (size_t)NE * Hd * Id * 2) return;
    int p = (int)(idx & 1);
    int i = (int)((idx >> 1) & 511);
    int h = (int)((idx >> 10) & 1023);
    int e = (int)(idx >> 20);
    const float* src = p ? uw : gw;
    float w = src[(((size_t)e << 10) + h) * Id + i];
    __nv_bfloat16 h_, l_; splitf(w, h_, l_);
    __nv_bfloat16* q = g_guT + ((size_t)e * 1024 + 2*i + p) * K3H + 3*h;
    q[0] = h_; q[1] = h_; q[2] = l_;
}

// dw3T[e][h][3i..] = tripletB(dw[e][i][h])
__global__ void build_dw3T(const float* __restrict__ dw) {
    size_t idx = (size_t)blockIdx.x * 256 + threadIdx.x;
    if (idx >= (size_t)NE * Id * Hd) return;
    int h = (int)(idx & 1023);
    int i = (int)((idx >> 10) & 511);
    int e = (int)(idx >> 19);
    float w = dw[(((size_t)e << 9) + i) * Hd + h];
    __nv_bfloat16 h_, l_; splitf(w, h_, l_);
    __nv_bfloat16* q = g_dw3T + ((size_t)e * Hd + h) * K3I + 3*i;
    q[0] = h_; q[1] = h_; q[2] = l_;
}

// ---------------- mma.sync GEMM ----------------
enum { M_SH_GATE = 0, M_SH_UP, M_SH_DOWN, M_R_GU, M_R_DOWN };

template <int MODE>
__global__ void __launch_bounds__(256, 2) mmak(const float* __restrict__ X,
                                               float* __restrict__ OUT) {
    constexpr int K3 = (MODE == M_SH_GATE) ? K3C
                     : (MODE == M_SH_UP || MODE == M_R_GU) ? K3H : K3I;
    constexpr int NK = K3 / 32;
    constexpr int BROWS = (MODE == M_R_GU || MODE == M_R_DOWN) ? 1024 : 0;

    int tileM = blockIdx.x, nb = blockIdx.y;
    if constexpr (MODE == M_R_GU || MODE == M_R_DOWN) {
        if (tileM >= g_ntiles) return;
    }

    __shared__ __align__(16) char smem[3 * 16384];
    unsigned smbase = smem_u32(smem);

    int tid = threadIdx.x;
    int warp = tid >> 5, lane = tid & 31;
    int wm = warp & 3, wn = warp >> 2;

    // B base (expert slice for routed)
    const __nv_bfloat16* Bb_;
    if constexpr (MODE == M_SH_GATE)      Bb_ = g_wp3T;
    else if constexpr (MODE == M_SH_UP)   Bb_ = g_su3T;
    else if constexpr (MODE == M_SH_DOWN) Bb_ = g_sd3T;
    else if constexpr (MODE == M_R_GU)    Bb_ = g_guT  + (size_t)g_tile_expert[tileM] * BROWS * K3;
    else                                  Bb_ = g_dw3T + (size_t)g_tile_expert[tileM] * BROWS * K3;

    // per-thread load slots: 2 A chunks + 2 B chunks of 16B
    int cA[2], jrow[2];
    const __nv_bfloat16* pA[2];
    const __nv_bfloat16* pB[2];
    unsigned oA[2], oB[2];
#pragma unroll
    for (int t = 0; t < 2; t++) {
        int id = tid + 256 * t;
        int r = id >> 2, c = id & 3;
        cA[t] = c;
        int rowg = tileM * 128 + r;
        if constexpr (MODE == M_SH_GATE || MODE == M_SH_UP) {
            int b = rowg >> 12, s = rowg & 4095;
            jrow[t] = b * SP + s;
            pA[t] = g_x3 + ((size_t)(jrow[t] + 2)) * K3H + c * 8;  // used by SH_UP only
        } else if constexpr (MODE == M_R_GU) {
            // indirect gather: token row lives in g_x3 at tok + 2*(tok>>12) + 2
            int tok = g_as_tok[rowg];
            int jr = tok + 2 * (tok >> 12) + 2;
            pA[t] = g_x3 + (size_t)jr * K3H + c * 8;
        } else if constexpr (MODE == M_SH_DOWN) {
            pA[t] = g_shact3 + (size_t)rowg * K3I + c * 8;
        } else {
            pA[t] = g_act3 + (size_t)rowg * K3I + c * 8;
        }
        pB[t] = Bb_ + (size_t)(nb * 128 + r) * K3 + c * 8;
        unsigned sw = (unsigned)(c ^ ((r >> 1) & 3));
        oA[t] = (unsigned)(r * 64) + (sw << 4);
        oB[t] = 8192u + (unsigned)(r * 64) + (sw << 4);
    }

    auto ldst = [&](int kt, int st) {
        unsigned sb = smbase + st * 16384;
#pragma unroll
        for (int t = 0; t < 2; t++) {
            const __nv_bfloat16* ga;
            if constexpr (MODE == M_SH_GATE) {
                int ko = kt * 32 + cA[t] * 8;
                int sh = (ko >= 2 * K3H) ? 2 : (ko >= K3H ? 1 : 0);
                ga = g_x3 + (size_t)(jrow[t] + sh) * K3H + (ko - sh * K3H);
            } else {
                ga = pA[t] + kt * 32;
            }
            cpa16(sb + oA[t], ga);
            cpa16(sb + oB[t], pB[t] + kt * 32);
        }
        asm volatile("cp.async.commit_group;" ::: "memory");
    };

    float acc[2][8][4];
#pragma unroll
    for (int a = 0; a < 2; a++)
#pragma unroll
        for (int b = 0; b < 8; b++)
#pragma unroll
            for (int c = 0; c < 4; c++) acc[a][b][c] = 0.f;

    ldst(0, 0);
    ldst(1, 1);

    int idx = lane >> 3;
    int rr = (lane & 7) + 8 * (idx & 1);
    int kb = idx >> 1;

    for (int kt = 0; kt < NK; kt++) {
        int st = kt % 3;
        if (kt + 1 < NK) { asm volatile("cp.async.wait_group 1;" ::: "memory"); }
        else             { asm volatile("cp.async.wait_group 0;" ::: "memory"); }
        __syncthreads();
        if (kt + 2 < NK) ldst(kt + 2, (kt + 2) % 3);

        unsigned sA = smbase + st * 16384, sB = sA + 8192;
#pragma unroll
        for (int kc = 0; kc < 2; kc++) {
            int kch = kc * 2 + kb;
            unsigned af[2][4], bfr[4][4];
#pragma unroll
            for (int mt = 0; mt < 2; mt++) {
                int r = wm * 32 + mt * 16 + rr;
                ldsm4(af[mt], sA + r * 64 + ((unsigned)(kch ^ ((r >> 1) & 3)) << 4));
            }
#pragma unroll
            for (int nt2 = 0; nt2 < 4; nt2++) {
                int rn = wn * 64 + nt2 * 16 + rr;
                ldsm4(bfr[nt2], sB + rn * 64 + ((unsigned)(kch ^ ((rn >> 1) & 3)) << 4));
            }
#pragma unroll
            for (int mt = 0; mt < 2; mt++)
#pragma unroll
                for (int nt = 0; nt < 8; nt++)
                    mma16816(acc[mt][nt], af[mt], bfr[nt >> 1][nt & 1], bfr[nt >> 1][2 + (nt & 1)]);
        }
    }

    // ---------------- epilogue ----------------
    int l2 = lane >> 2, l4 = lane & 3;
#pragma unroll
    for (int mt = 0; mt < 2; mt++) {
#pragma unroll
        for (int hh = 0; hh < 2; hh++) {
            int rowg = tileM * 128 + wm * 32 + mt * 16 + l2 + 8 * hh;
            if constexpr (MODE == M_R_DOWN) {
                float w = g_as_w[rowg];
                if (w != 0.f) {
                    int tok = g_as_tok[rowg];
                    float* dst = OUT + (size_t)tok * Hd;
#pragma unroll
                    for (int nt = 0; nt < 8; nt++) {
                        int colg = nb * 128 + wn * 64 + nt * 8 + l4 * 2;
                        atomicAdd(dst + colg,     w * acc[mt][nt][2*hh]);
                        atomicAdd(dst + colg + 1, w * acc[mt][nt][2*hh + 1]);
                    }
                }
            } else if constexpr (MODE == M_SH_DOWN) {
                float w = g_wid[rowg];
                const float* xr = X + (size_t)rowg * Hd;
                float* dst = OUT + (size_t)rowg * Hd;
#pragma unroll
                for (int nt = 0; nt < 8; nt++) {
                    int colg = nb * 128 + wn * 64 + nt * 8 + l4 * 2;
                    float2 xv = *(const float2*)(xr + colg);
                    float2 o;
                    o.x = acc[mt][nt][2*hh]     + w * xv.x;
                    o.y = acc[mt][nt][2*hh + 1] + w * xv.y;
                    *(float2*)(dst + colg) = o;
                }
            } else if constexpr (MODE == M_SH_GATE) {
                float* dst = g_shact + (size_t)rowg * Id;
#pragma unroll
                for (int nt = 0; nt < 8; nt++) {
                    int colg = nb * 128 + wn * 64 + nt * 8 + l4 * 2;
                    *(float2*)(dst + colg) =
                        make_float2(acc[mt][nt][2*hh], acc[mt][nt][2*hh + 1]);
                }
            } else if constexpr (MODE == M_SH_UP) {
                const float* gs = g_shact + (size_t)rowg * Id;
                __nv_bfloat16* d3 = g_shact3 + (size_t)rowg * K3I;
#pragma unroll
                for (int nt = 0; nt < 8; nt++) {
                    int colg = nb * 128 + wn * 64 + nt * 8 + l4 * 2;
                    float2 g = *(const float2*)(gs + colg);
                    float v0 = silu_f(g.x) * acc[mt][nt][2*hh];
                    float v1 = silu_f(g.y) * acc[mt][nt][2*hh + 1];
                    __nv_bfloat16 h0,l0,h1,l1; splitf(v0,h0,l0); splitf(v1,h1,l1);
                    unsigned* p = (unsigned*)(d3 + 3 * colg);
                    p[0] = pkbf(h0,l0); p[1] = pkbf(h0,h1); p[2] = pkbf(l1,h1);
                }
            } else {  // M_R_GU: interleaved (gate, up) column pairs
                __nv_bfloat16* d3 = g_act3 + (size_t)rowg * K3I;
#pragma unroll
                for (int nt = 0; nt < 8; nt++) {
                    int i = nb * 64 + wn * 32 + nt * 4 + l4;   // value column
                    float v = silu_f(acc[mt][nt][2*hh]) * acc[mt][nt][2*hh + 1];
                    __nv_bfloat16 h_, l_; splitf(v, h_, l_);
                    __nv_bfloat16* p = d3 + 3 * i;
                    p[0] = h_; p[1] = l_; p[2] = h_;
                }
            }
        }
    }
}

// ---------------- launch ----------------
extern "C" void kernel_launch(void* const* d_in, const int* in_sizes, int n_in,
                              void* d_out, int out_size) {
    (void)in_sizes; (void)n_in; (void)out_size;
    const float* x   = (const float*)d_in[0];
    const float* rw  = (const float*)d_in[1];
    const float* rb  = (const float*)d_in[2];
    const float* gw  = (const float*)d_in[3];
    const float* uw  = (const float*)d_in[4];
    const float* dw  = (const float*)d_in[5];
    const float* cw  = (const float*)d_in[6];
    const float* suw = (const float*)d_in[7];
    const float* sdw = (const float*)d_in[8];
    float* out = (float*)d_out;

    // routing
    zero_meta<<<1, 32>>>();
    router_kernel<<<Tn / 8, 256>>>(x, rw, rb);
    prefix_kernel<<<1, 32>>>();
    fill_assign<<<(MAXROWS + 255) / 256, 256>>>();
    assign_kernel<<<Tn / 256, 256>>>();

    // triplet expansions (no gather pass: routed GEMMs read g_x3 indirectly)
    {
        size_t n;
        n = (size_t)Bb * SP * Hd / 2;   expand_x3 <<<(unsigned)((n + 255) / 256), 256>>>(x);
        n = (size_t)Id * Hd * 3;        build_wp3T<<<(unsigned)((n + 255) / 256), 256>>>(cw);
        n = (size_t)Hd * Id;            build_su3T<<<(unsigned)((n + 255) / 256), 256>>>(suw);
        n = (size_t)Id * Hd;            build_sd3T<<<(unsigned)((n + 255) / 256), 256>>>(sdw);
        n = (size_t)NE * Hd * Id * 2;   build_guT <<<(unsigned)((n + 255) / 256), 256>>>(gw, uw);
        n = (size_t)NE * Id * Hd;       build_dw3T<<<(unsigned)((n + 255) / 256), 256>>>(dw);
    }

    // shared expert: conv-gate -> up(*silu) -> down(+identity expert)
    mmak<M_SH_GATE><<<dim3(Tn / 128, Id / 128), 256>>>(x, out);
    mmak<M_SH_UP>  <<<dim3(Tn / 128, Id / 128), 256>>>(x, out);
    mmak<M_SH_DOWN><<<dim3(Tn / 128, Hd / 128), 256>>>(x, out);

    // routed experts: fused gate+up (interleaved cols), then weighted scatter down
    mmak<M_R_GU>   <<<dim3(MAX_TILES, 1024 / 128), 256>>>(x, out);
    mmak<M_R_DOWN> <<<dim3(MAX_TILES, Hd / 128), 256>>>(x, out);
}

// round 9
// speedup vs baseline: 2.8019x; 1.7325x over previous
#include <cuda_runtime.h>
#include <cuda_fp16.h>
#include <math.h>
#include <stdint.h>

#define DINLINE __device__ __forceinline__

// ---------------- problem constants ----------------
constexpr int Bb = 4;
constexpr int Sq = 4096;
constexpr int Hd = 1024;
constexpr int Id = 512;
constexpr int NE = 15;                      // routed experts (idx 15 = identity)
constexpr int Tn = Bb * Sq;                 // 16384
constexpr int SP = Sq + 2;                  // left-padded seq (conv)
constexpr int MAXROWS = 2 * Tn + NE * 128;  // 34688
constexpr int MAX_TILES = MAXROWS / 128;    // 271

// pair-expanded K sizes (fp16 2-product: A=(hi,lo), B=(hi,hi))
constexpr int K2H = 2 * Hd;    // 2048
constexpr int K2I = 2 * Id;    // 1024
constexpr int K2C = 6 * Hd;    // 6144 (conv: 3 shifts x 2048)

// ---------------- device scratch ----------------
__device__ __align__(16) __half g_x2[(size_t)Bb * SP * K2H];     // padded x, pair
__device__ __align__(16) __half g_shact2[(size_t)Tn * K2I];      // shared silu*up
__device__ __align__(16) __half g_act2[(size_t)MAXROWS * K2I];   // routed silu*up
__device__ __align__(16) float  g_shact[(size_t)Tn * Id];        // shared conv gate fp32
__device__ __align__(16) __half g_wp2T[(size_t)Id * K2C];        // conv W, B-layout
__device__ __align__(16) __half g_su2T[(size_t)Id * K2H];
__device__ __align__(16) __half g_sd2T[(size_t)Hd * K2I];
__device__ __align__(16) __half g_guT[(size_t)NE * 1024 * K2H];  // interleaved gate/up
__device__ __align__(16) __half g_dw2T[(size_t)NE * Hd * K2I];

__device__ int   g_top_idx[Tn * 2];
__device__ float g_top_w[Tn * 2];
__device__ float g_wid[Tn];
__device__ int   g_counts[NE];
__device__ int   g_cursor[NE];
__device__ int   g_off[NE + 1];
__device__ int   g_tile_expert[MAX_TILES];
__device__ int   g_ntiles;
__device__ int   g_as_tok[MAXROWS];
__device__ float g_as_w[MAXROWS];

// ---------------- helpers ----------------
DINLINE float silu_f(float g) { return g / (1.f + expf(-g)); }
DINLINE void splith(float v, __half& h, __half& l) {
    h = __float2half(v);
    l = __float2half(v - __half2float(h));
}
DINLINE unsigned pkh(__half a, __half b) {
    unsigned short ua = *(unsigned short*)&a, ub = *(unsigned short*)&b;
    return (unsigned)ua | ((unsigned)ub << 16);
}

DINLINE unsigned smem_u32(const void* p) {
    unsigned a;
    asm("{ .reg .u64 t; cvta.to.shared.u64 t, %1; cvt.u32.u64 %0, t; }" : "=r"(a) : "l"(p));
    return a;
}
DINLINE void cpa16(unsigned d, const void* g) {
    asm volatile("cp.async.cg.shared.global [%0], [%1], 16;" :: "r"(d), "l"(g) : "memory");
}
DINLINE void ldsm4(unsigned* r, unsigned a) {
    asm volatile("ldmatrix.sync.aligned.m8n8.x4.shared.b16 {%0,%1,%2,%3}, [%4];"
        : "=r"(r[0]), "=r"(r[1]), "=r"(r[2]), "=r"(r[3]) : "r"(a));
}
DINLINE void mma16816(float* c, const unsigned* a, unsigned b0, unsigned b1) {
    asm volatile(
        "mma.sync.aligned.m16n8k16.row.col.f32.f16.f16.f32 "
        "{%0,%1,%2,%3}, {%4,%5,%6,%7}, {%8,%9}, {%0,%1,%2,%3};"
        : "+f"(c[0]), "+f"(c[1]), "+f"(c[2]), "+f"(c[3])
        : "r"(a[0]), "r"(a[1]), "r"(a[2]), "r"(a[3]), "r"(b0), "r"(b1));
}

// ---------------- routing kernels ----------------
__global__ void zero_meta() {
    int t = threadIdx.x;
    if (t < NE) { g_counts[t] = 0; g_cursor[t] = 0; }
}

__global__ void router_kernel(const float* __restrict__ x,
                              const float* __restrict__ rw,
                              const float* __restrict__ rb) {
    int gw = (blockIdx.x * blockDim.x + threadIdx.x) >> 5;
    int lane = threadIdx.x & 31;
    if (gw >= Tn) return;
    const float* xr = x + (size_t)gw * Hd;
    float acc[16];
#pragma unroll
    for (int e = 0; e < 16; e++) acc[e] = 0.f;
    for (int h = lane; h < Hd; h += 32) {
        float xv = xr[h];
        const float4* w4 = (const float4*)(rw + (size_t)h * 16);
        float4 w0 = w4[0], w1 = w4[1], w2 = w4[2], w3 = w4[3];
        acc[0] += xv*w0.x;  acc[1] += xv*w0.y;  acc[2] += xv*w0.z;  acc[3] += xv*w0.w;
        acc[4] += xv*w1.x;  acc[5] += xv*w1.y;  acc[6] += xv*w1.z;  acc[7] += xv*w1.w;
        acc[8] += xv*w2.x;  acc[9] += xv*w2.y;  acc[10]+= xv*w2.z;  acc[11]+= xv*w2.w;
        acc[12]+= xv*w3.x;  acc[13]+= xv*w3.y;  acc[14]+= xv*w3.z;  acc[15]+= xv*w3.w;
    }
#pragma unroll
    for (int e = 0; e < 16; e++) {
#pragma unroll
        for (int o = 16; o > 0; o >>= 1) acc[e] += __shfl_xor_sync(0xffffffffu, acc[e], o);
    }
    if (lane == 0) {
        float l[16]; float m = -1e30f;
#pragma unroll
        for (int e = 0; e < 16; e++) { l[e] = acc[e] + rb[e]; m = fmaxf(m, l[e]); }
        float p[16]; float s = 0.f;
#pragma unroll
        for (int e = 0; e < 16; e++) { p[e] = expf(l[e] - m); s += p[e]; }
        int i1 = 0; float p1 = p[0];
#pragma unroll
        for (int e = 1; e < 16; e++) if (p[e] > p1) { p1 = p[e]; i1 = e; }
        int i2 = -1; float p2 = -1e30f;
#pragma unroll
        for (int e = 0; e < 16; e++) if (e != i1 && p[e] > p2) { p2 = p[e]; i2 = e; }
        float pr1 = p1 / s, pr2 = p2 / s;
        float d = pr1 + pr2 + 1e-6f;
        float w1 = pr1 / d, w2 = pr2 / d;
        g_top_idx[gw*2] = i1; g_top_idx[gw*2+1] = i2;
        g_top_w[gw*2] = w1;   g_top_w[gw*2+1] = w2;
        float wid = 0.f;
        if (i1 == NE) wid = w1; else if (i2 == NE) wid = w2;
        g_wid[gw] = wid;
        if (i1 < NE) atomicAdd(&g_counts[i1], 1);
        if (i2 < NE) atomicAdd(&g_counts[i2], 1);
    }
}

__global__ void prefix_kernel() {
    if (threadIdx.x == 0 && blockIdx.x == 0) {
        int off = 0;
        for (int e = 0; e < NE; e++) {
            g_off[e] = off;
            int a = (g_counts[e] + 127) & ~127;
            for (int t = off >> 7; t < (off + a) >> 7; t++) g_tile_expert[t] = e;
            off += a;
        }
        g_off[NE] = off;
        g_ntiles = off >> 7;
    }
}

__global__ void fill_assign() {
    int i = blockIdx.x * blockDim.x + threadIdx.x;
    if (i < MAXROWS) { g_as_tok[i] = 0; g_as_w[i] = 0.f; }
}

__global__ void assign_kernel() {
    int t = blockIdx.x * blockDim.x + threadIdx.x;
    if (t >= Tn) return;
#pragma unroll
    for (int k = 0; k < 2; k++) {
        int e = g_top_idx[t*2 + k];
        if (e < NE) {
            int p = atomicAdd(&g_cursor[e], 1);
            int r = g_off[e] + p;
            g_as_tok[r] = t;
            g_as_w[r] = g_top_w[t*2 + k];
        }
    }
}

// ---------------- pair expansion kernels ----------------
// A-pattern pair: (hi, lo).  B-pattern pair: (hi, hi).

// g_x2[rj][2h..] = pairA(x[b][rj%SP - 2][h]), zeros for first 2 rows
__global__ void expand_x2(const float* __restrict__ x) {
    size_t i = (size_t)blockIdx.x * 256 + threadIdx.x;
    if (i >= (size_t)Bb * SP * Hd / 2) return;
    size_t e = i * 2;
    int h = (int)(e & 1023);
    int rj = (int)(e >> 10);
    int r = rj % SP, b = rj / SP;
    float2 v = make_float2(0.f, 0.f);
    if (r >= 2) v = *(const float2*)(x + (((size_t)(b * Sq + r - 2)) << 10) + h);
    __half h0,l0,h1,l1; splith(v.x,h0,l0); splith(v.y,h1,l1);
    uint2* p = (uint2*)(g_x2 + (size_t)rj * K2H + 2*h);
    *p = make_uint2(pkh(h0,l0), pkh(h1,l1));
}

// conv W: wp2T[i][kk*2048 + 2h..] = pairB(cw[i][h][kk])
__global__ void build_wp2T(const float* __restrict__ cw) {
    int idx = blockIdx.x * 256 + threadIdx.x;
    if (idx >= Id * Hd * 3) return;
    int kk = idx % 3, hh = (idx / 3) & 1023, ii = idx / 3072;
    __half h_ = __float2half(cw[(size_t)ii * 3072 + hh * 3 + kk]);
    unsigned* q = (unsigned*)(g_wp2T + (size_t)ii * K2C + kk * K2H + 2*hh);
    *q = pkh(h_, h_);
}

// su2T[i][2h..] = pairB(suw[h][i])
__global__ void build_su2T(const float* __restrict__ suw) {
    int idx = blockIdx.x * 256 + threadIdx.x;
    if (idx >= Hd * Id) return;
    int i = idx & 511, h = idx >> 9;
    __half h_ = __float2half(suw[(size_t)h * Id + i]);
    unsigned* q = (unsigned*)(g_su2T + (size_t)i * K2H + 2*h);
    *q = pkh(h_, h_);
}

// sd2T[h][2i..] = pairB(sdw[i][h])
__global__ void build_sd2T(const float* __restrict__ sdw) {
    int idx = blockIdx.x * 256 + threadIdx.x;
    if (idx >= Id * Hd) return;
    int h = idx & 1023, i = idx >> 10;
    __half h_ = __float2half(sdw[(size_t)i * Hd + h]);
    unsigned* q = (unsigned*)(g_sd2T + (size_t)h * K2I + 2*i);
    *q = pkh(h_, h_);
}

// guT[e][2i+p][2h..] = pairB( (p? uw : gw)[e][h][i] )
__global__ void build_guT(const float* __restrict__ gw, const float* __restrict__ uw) {
    size_t idx = (size_t)blockIdx.x * 256 + threadIdx.x;
    if (idx >= (size_t)NE * Hd * Id * 2) return;
    int p = (int)(idx & 1);
    int i = (int)((idx >> 1) & 511);
    int h = (int)((idx >> 10) & 1023);
    int e = (int)(idx >> 20);
    const float* src = p ? uw : gw;
    __half h_ = __float2half(src[(((size_t)e << 10) + h) * Id + i]);
    unsigned* q = (unsigned*)(g_guT + ((size_t)e * 1024 + 2*i + p) * K2H + 2*h);
    *q = pkh(h_, h_);
}

// dw2T[e][h][2i..] = pairB(dw[e][i][h])
__global__ void build_dw2T(const float* __restrict__ dw) {
    size_t idx = (size_t)blockIdx.x * 256 + threadIdx.x;
    if (idx >= (size_t)NE * Id * Hd) return;
    int h = (int)(idx & 1023);
    int i = (int)((idx >> 10) & 511);
    int e = (int)(idx >> 19);
    __half h_ = __float2half(dw[(((size_t)e << 9) + i) * Hd + h]);
    unsigned* q = (unsigned*)(g_dw2T + ((size_t)e * Hd + h) * K2I + 2*i);
    *q = pkh(h_, h_);
}

// ---------------- mma.sync GEMM ----------------
enum { M_SH_GATE = 0, M_SH_UP, M_SH_DOWN, M_R_GU, M_R_DOWN };

template <int MODE>
__global__ void __launch_bounds__(256, 2) mmak(const float* __restrict__ X,
                                               float* __restrict__ OUT) {
    constexpr int K2 = (MODE == M_SH_GATE) ? K2C
                     : (MODE == M_SH_UP || MODE == M_R_GU) ? K2H : K2I;
    constexpr int NK = K2 / 32;
    constexpr int BROWS = (MODE == M_R_GU || MODE == M_R_DOWN) ? 1024 : 0;

    int tileM = blockIdx.x, nb = blockIdx.y;
    if constexpr (MODE == M_R_GU || MODE == M_R_DOWN) {
        if (tileM >= g_ntiles) return;
    }

    __shared__ __align__(16) char smem[3 * 16384];
    unsigned smbase = smem_u32(smem);

    int tid = threadIdx.x;
    int warp = tid >> 5, lane = tid & 31;
    int wm = warp & 3, wn = warp >> 2;

    // B base (expert slice for routed)
    const __half* Bb_;
    if constexpr (MODE == M_SH_GATE)      Bb_ = g_wp2T;
    else if constexpr (MODE == M_SH_UP)   Bb_ = g_su2T;
    else if constexpr (MODE == M_SH_DOWN) Bb_ = g_sd2T;
    else if constexpr (MODE == M_R_GU)    Bb_ = g_guT  + (size_t)g_tile_expert[tileM] * BROWS * K2;
    else                                  Bb_ = g_dw2T + (size_t)g_tile_expert[tileM] * BROWS * K2;

    // per-thread load slots: 2 A chunks + 2 B chunks of 16B
    int cA[2], jrow[2];
    const __half* pA[2];
    const __half* pB[2];
    unsigned oA[2], oB[2];
#pragma unroll
    for (int t = 0; t < 2; t++) {
        int id = tid + 256 * t;
        int r = id >> 2, c = id & 3;
        cA[t] = c;
        int rowg = tileM * 128 + r;
        if constexpr (MODE == M_SH_GATE || MODE == M_SH_UP) {
            int b = rowg >> 12, s = rowg & 4095;
            jrow[t] = b * SP + s;
            pA[t] = g_x2 + ((size_t)(jrow[t] + 2)) * K2H + c * 8;  // used by SH_UP only
        } else if constexpr (MODE == M_R_GU) {
            // indirect gather: token row lives in g_x2 at tok + 2*(tok>>12) + 2
            int tok = g_as_tok[rowg];
            int jr = tok + 2 * (tok >> 12) + 2;
            pA[t] = g_x2 + (size_t)jr * K2H + c * 8;
        } else if constexpr (MODE == M_SH_DOWN) {
            pA[t] = g_shact2 + (size_t)rowg * K2I + c * 8;
        } else {
            pA[t] = g_act2 + (size_t)rowg * K2I + c * 8;
        }
        pB[t] = Bb_ + (size_t)(nb * 128 + r) * K2 + c * 8;
        unsigned sw = (unsigned)(c ^ ((r >> 1) & 3));
        oA[t] = (unsigned)(r * 64) + (sw << 4);
        oB[t] = 8192u + (unsigned)(r * 64) + (sw << 4);
    }

    auto ldst = [&](int kt, int st) {
        unsigned sb = smbase + st * 16384;
#pragma unroll
        for (int t = 0; t < 2; t++) {
            const __half* ga;
            if constexpr (MODE == M_SH_GATE) {
                int ko = kt * 32 + cA[t] * 8;
                int sh = (ko >= 2 * K2H) ? 2 : (ko >= K2H ? 1 : 0);
                ga = g_x2 + (size_t)(jrow[t] + sh) * K2H + (ko - sh * K2H);
            } else {
                ga = pA[t] + kt * 32;
            }
            cpa16(sb + oA[t], ga);
            cpa16(sb + oB[t], pB[t] + kt * 32);
        }
        asm volatile("cp.async.commit_group;" ::: "memory");
    };

    float acc[2][8][4];
#pragma unroll
    for (int a = 0; a < 2; a++)
#pragma unroll
        for (int b = 0; b < 8; b++)
#pragma unroll
            for (int c = 0; c < 4; c++) acc[a][b][c] = 0.f;

    ldst(0, 0);
    ldst(1, 1);

    int idx = lane >> 3;
    int rr = (lane & 7) + 8 * (idx & 1);
    int kb = idx >> 1;

    for (int kt = 0; kt < NK; kt++) {
        int st = kt % 3;
        if (kt + 1 < NK) { asm volatile("cp.async.wait_group 1;" ::: "memory"); }
        else             { asm volatile("cp.async.wait_group 0;" ::: "memory"); }
        __syncthreads();
        if (kt + 2 < NK) ldst(kt + 2, (kt + 2) % 3);

        unsigned sA = smbase + st * 16384, sB = sA + 8192;
#pragma unroll
        for (int kc = 0; kc < 2; kc++) {
            int kch = kc * 2 + kb;
            unsigned af[2][4], bfr[4][4];
#pragma unroll
            for (int mt = 0; mt < 2; mt++) {
                int r = wm * 32 + mt * 16 + rr;
                ldsm4(af[mt], sA + r * 64 + ((unsigned)(kch ^ ((r >> 1) & 3)) << 4));
            }
#pragma unroll
            for (int nt2 = 0; nt2 < 4; nt2++) {
                int rn = wn * 64 + nt2 * 16 + rr;
                ldsm4(bfr[nt2], sB + rn * 64 + ((unsigned)(kch ^ ((rn >> 1) & 3)) << 4));
            }
#pragma unroll
            for (int mt = 0; mt < 2; mt++)
#pragma unroll
                for (int nt = 0; nt < 8; nt++)
                    mma16816(acc[mt][nt], af[mt], bfr[nt >> 1][nt & 1], bfr[nt >> 1][2 + (nt & 1)]);
        }
    }

    // ---------------- epilogue ----------------
    int l2 = lane >> 2, l4 = lane & 3;
#pragma unroll
    for (int mt = 0; mt < 2; mt++) {
#pragma unroll
        for (int hh = 0; hh < 2; hh++) {
            int rowg = tileM * 128 + wm * 32 + mt * 16 + l2 + 8 * hh;
            if constexpr (MODE == M_R_DOWN) {
                float w = g_as_w[rowg];
                if (w != 0.f) {
                    int tok = g_as_tok[rowg];
                    float* dst = OUT + (size_t)tok * Hd;
#pragma unroll
                    for (int nt = 0; nt < 8; nt++) {
                        int colg = nb * 128 + wn * 64 + nt * 8 + l4 * 2;
                        atomicAdd(dst + colg,     w * acc[mt][nt][2*hh]);
                        atomicAdd(dst + colg + 1, w * acc[mt][nt][2*hh + 1]);
                    }
                }
            } else if constexpr (MODE == M_SH_DOWN) {
                float w = g_wid[rowg];
                const float* xr = X + (size_t)rowg * Hd;
                float* dst = OUT + (size_t)rowg * Hd;
#pragma unroll
                for (int nt = 0; nt < 8; nt++) {
                    int colg = nb * 128 + wn * 64 + nt * 8 + l4 * 2;
                    float2 xv = *(const float2*)(xr + colg);
                    float2 o;
                    o.x = acc[mt][nt][2*hh]     + w * xv.x;
                    o.y = acc[mt][nt][2*hh + 1] + w * xv.y;
                    *(float2*)(dst + colg) = o;
                }
            } else if constexpr (MODE == M_SH_GATE) {
                float* dst = g_shact + (size_t)rowg * Id;
#pragma unroll
                for (int nt = 0; nt < 8; nt++) {
                    int colg = nb * 128 + wn * 64 + nt * 8 + l4 * 2;
                    *(float2*)(dst + colg) =
                        make_float2(acc[mt][nt][2*hh], acc[mt][nt][2*hh + 1]);
                }
            } else if constexpr (MODE == M_SH_UP) {
                const float* gs = g_shact + (size_t)rowg * Id;
                __half* d2 = g_shact2 + (size_t)rowg * K2I;
#pragma unroll
                for (int nt = 0; nt < 8; nt++) {
                    int colg = nb * 128 + wn * 64 + nt * 8 + l4 * 2;
                    float2 g = *(const float2*)(gs + colg);
                    float v0 = silu_f(g.x) * acc[mt][nt][2*hh];
                    float v1 = silu_f(g.y) * acc[mt][nt][2*hh + 1];
                    __half h0,l0,h1,l1; splith(v0,h0,l0); splith(v1,h1,l1);
                    uint2* p = (uint2*)(d2 + 2 * colg);
                    *p = make_uint2(pkh(h0,l0), pkh(h1,l1));
                }
            } else {  // M_R_GU: interleaved (gate, up) column pairs
                __half* d2 = g_act2 + (size_t)rowg * K2I;
#pragma unroll
                for (int nt = 0; nt < 8; nt++) {
                    int i = nb * 64 + wn * 32 + nt * 4 + l4;   // value column
                    float v = silu_f(acc[mt][nt][2*hh]) * acc[mt][nt][2*hh + 1];
                    __half h_, l_; splith(v, h_, l_);
                    unsigned* p = (unsigned*)(d2 + 2 * i);
                    *p = pkh(h_, l_);
                }
            }
        }
    }
}

// ---------------- launch ----------------
extern "C" void kernel_launch(void* const* d_in, const int* in_sizes, int n_in,
                              void* d_out, int out_size) {
    (void)in_sizes; (void)n_in; (void)out_size;
    const float* x   = (const float*)d_in[0];
    const float* rw  = (const float*)d_in[1];
    const float* rb  = (const float*)d_in[2];
    const float* gw  = (const float*)d_in[3];
    const float* uw  = (const float*)d_in[4];
    const float* dw  = (const float*)d_in[5];
    const float* cw  = (const float*)d_in[6];
    const float* suw = (const float*)d_in[7];
    const float* sdw = (const float*)d_in[8];
    float* out = (float*)d_out;

    // routing
    zero_meta<<<1, 32>>>();
    router_kernel<<<Tn / 8, 256>>>(x, rw, rb);
    prefix_kernel<<<1, 32>>>();
    fill_assign<<<(MAXROWS + 255) / 256, 256>>>();
    assign_kernel<<<Tn / 256, 256>>>();

    // pair expansions (no gather pass: routed GEMMs read g_x2 indirectly)
    {
        size_t n;
        n = (size_t)Bb * SP * Hd / 2;   expand_x2 <<<(unsigned)((n + 255) / 256), 256>>>(x);
        n = (size_t)Id * Hd * 3;        build_wp2T<<<(unsigned)((n + 255) / 256), 256>>>(cw);
        n = (size_t)Hd * Id;            build_su2T<<<(unsigned)((n + 255) / 256), 256>>>(suw);
        n = (size_t)Id * Hd;            build_sd2T<<<(unsigned)((n + 255) / 256), 256>>>(sdw);
        n = (size_t)NE * Hd * Id * 2;   build_guT <<<(unsigned)((n + 255) / 256), 256>>>(gw, uw);
        n = (size_t)NE * Id * Hd;       build_dw2T<<<(unsigned)((n + 255) / 256), 256>>>(dw);
    }

    // shared expert: conv-gate -> up(*silu) -> down(+identity expert)
    mmak<M_SH_GATE><<<dim3(Tn / 128, Id / 128), 256>>>(x, out);
    mmak<M_SH_UP>  <<<dim3(Tn / 128, Id / 128), 256>>>(x, out);
    mmak<M_SH_DOWN><<<dim3(Tn / 128, Hd / 128), 256>>>(x, out);

    // routed experts: fused gate+up (interleaved cols), then weighted scatter down
    mmak<M_R_GU>   <<<dim3(MAX_TILES, 1024 / 128), 256>>>(x, out);
    mmak<M_R_DOWN> <<<dim3(MAX_TILES, Hd / 128), 256>>>(x, out);
}

// round 13
// speedup vs baseline: 4.2342x; 1.5112x over previous
#include <cuda_runtime.h>
#include <cuda_fp16.h>
#include <math.h>
#include <stdint.h>

#define DINLINE __device__ __forceinline__

// ---------------- problem constants ----------------
constexpr int Bb = 4;
constexpr int Sq = 4096;
constexpr int Hd = 1024;
constexpr int Id = 512;
constexpr int NE = 15;                      // routed experts (idx 15 = identity)
constexpr int Tn = Bb * Sq;                 // 16384
constexpr int SP = Sq + 2;                  // left-padded seq (conv)
constexpr int MAXROWS = 2 * Tn + NE * 128;  // 34688
constexpr int MAX_TILES = MAXROWS / 128;    // 271

// plain fp16 K sizes (single product)
constexpr int KH = Hd;         // 1024
constexpr int KI = Id;         // 512
constexpr int KC = 3 * Hd;     // 3072 (conv: 3 shifts x 1024)

// ---------------- device scratch ----------------
__device__ __align__(16) __half g_x1[(size_t)Bb * SP * KH];      // padded x fp16
__device__ __align__(16) __half g_shact1[(size_t)Tn * KI];       // shared silu*up fp16
__device__ __align__(16) __half g_act1[(size_t)MAXROWS * KI];    // routed silu*up fp16
__device__ __align__(16) float  g_shact[(size_t)Tn * Id];        // shared conv gate fp32
__device__ __align__(16) __half g_wpT[(size_t)Id * KC];          // conv W, B-layout
__device__ __align__(16) __half g_suT[(size_t)Id * KH];
__device__ __align__(16) __half g_sdT[(size_t)Hd * KI];
__device__ __align__(16) __half g_guT[(size_t)NE * 1024 * KH];   // interleaved gate/up
__device__ __align__(16) __half g_dwT[(size_t)NE * Hd * KI];

__device__ int   g_top_idx[Tn * 2];
__device__ float g_top_w[Tn * 2];
__device__ float g_wid[Tn];
__device__ int   g_counts[NE];
__device__ int   g_cursor[NE];
__device__ int   g_off[NE + 1];
__device__ int   g_tile_expert[MAX_TILES];
__device__ int   g_ntiles;
__device__ int   g_as_tok[MAXROWS];
__device__ float g_as_w[MAXROWS];

// ---------------- helpers ----------------
DINLINE float silu_f(float g) { return g / (1.f + expf(-g)); }
DINLINE unsigned pkh(__half a, __half b) {
    unsigned short ua = *(unsigned short*)&a, ub = *(unsigned short*)&b;
    return (unsigned)ua | ((unsigned)ub << 16);
}

DINLINE unsigned smem_u32(const void* p) {
    unsigned a;
    asm("{ .reg .u64 t; cvta.to.shared.u64 t, %1; cvt.u32.u64 %0, t; }" : "=r"(a) : "l"(p));
    return a;
}
DINLINE void cpa16(unsigned d, const void* g) {
    asm volatile("cp.async.cg.shared.global [%0], [%1], 16;" :: "r"(d), "l"(g) : "memory");
}
DINLINE void ldsm4(unsigned* r, unsigned a) {
    asm volatile("ldmatrix.sync.aligned.m8n8.x4.shared.b16 {%0,%1,%2,%3}, [%4];"
        : "=r"(r[0]), "=r"(r[1]), "=r"(r[2]), "=r"(r[3]) : "r"(a));
}
DINLINE void mma16816(float* c, const unsigned* a, unsigned b0, unsigned b1) {
    asm volatile(
        "mma.sync.aligned.m16n8k16.row.col.f32.f16.f16.f32 "
        "{%0,%1,%2,%3}, {%4,%5,%6,%7}, {%8,%9}, {%0,%1,%2,%3};"
        : "+f"(c[0]), "+f"(c[1]), "+f"(c[2]), "+f"(c[3])
        : "r"(a[0]), "r"(a[1]), "r"(a[2]), "r"(a[3]), "r"(b0), "r"(b1));
}

// ---------------- routing kernels ----------------
__global__ void zero_meta() {
    int t = threadIdx.x;
    if (t < NE) { g_counts[t] = 0; g_cursor[t] = 0; }
}

__global__ void router_kernel(const float* __restrict__ x,
                              const float* __restrict__ rw,
                              const float* __restrict__ rb) {
    int gw = (blockIdx.x * blockDim.x + threadIdx.x) >> 5;
    int lane = threadIdx.x & 31;
    if (gw >= Tn) return;
    const float* xr = x + (size_t)gw * Hd;
    float acc[16];
#pragma unroll
    for (int e = 0; e < 16; e++) acc[e] = 0.f;
    for (int h = lane; h < Hd; h += 32) {
        float xv = xr[h];
        const float4* w4 = (const float4*)(rw + (size_t)h * 16);
        float4 w0 = w4[0], w1 = w4[1], w2 = w4[2], w3 = w4[3];
        acc[0] += xv*w0.x;  acc[1] += xv*w0.y;  acc[2] += xv*w0.z;  acc[3] += xv*w0.w;
        acc[4] += xv*w1.x;  acc[5] += xv*w1.y;  acc[6] += xv*w1.z;  acc[7] += xv*w1.w;
        acc[8] += xv*w2.x;  acc[9] += xv*w2.y;  acc[10]+= xv*w2.z;  acc[11]+= xv*w2.w;
        acc[12]+= xv*w3.x;  acc[13]+= xv*w3.y;  acc[14]+= xv*w3.z;  acc[15]+= xv*w3.w;
    }
#pragma unroll
    for (int e = 0; e < 16; e++) {
#pragma unroll
        for (int o = 16; o > 0; o >>= 1) acc[e] += __shfl_xor_sync(0xffffffffu, acc[e], o);
    }
    if (lane == 0) {
        float l[16]; float m = -1e30f;
#pragma unroll
        for (int e = 0; e < 16; e++) { l[e] = acc[e] + rb[e]; m = fmaxf(m, l[e]); }
        float p[16]; float s = 0.f;
#pragma unroll
        for (int e = 0; e < 16; e++) { p[e] = expf(l[e] - m); s += p[e]; }
        int i1 = 0; float p1 = p[0];
#pragma unroll
        for (int e = 1; e < 16; e++) if (p[e] > p1) { p1 = p[e]; i1 = e; }
        int i2 = -1; float p2 = -1e30f;
#pragma unroll
        for (int e = 0; e < 16; e++) if (e != i1 && p[e] > p2) { p2 = p[e]; i2 = e; }
        float pr1 = p1 / s, pr2 = p2 / s;
        float d = pr1 + pr2 + 1e-6f;
        float w1 = pr1 / d, w2 = pr2 / d;
        g_top_idx[gw*2] = i1; g_top_idx[gw*2+1] = i2;
        g_top_w[gw*2] = w1;   g_top_w[gw*2+1] = w2;
        float wid = 0.f;
        if (i1 == NE) wid = w1; else if (i2 == NE) wid = w2;
        g_wid[gw] = wid;
        if (i1 < NE) atomicAdd(&g_counts[i1], 1);
        if (i2 < NE) atomicAdd(&g_counts[i2], 1);
    }
}

__global__ void prefix_kernel() {
    if (threadIdx.x == 0 && blockIdx.x == 0) {
        int off = 0;
        for (int e = 0; e < NE; e++) {
            g_off[e] = off;
            int a = (g_counts[e] + 127) & ~127;
            for (int t = off >> 7; t < (off + a) >> 7; t++) g_tile_expert[t] = e;
            off += a;
        }
        g_off[NE] = off;
        g_ntiles = off >> 7;
    }
}

__global__ void fill_assign() {
    int i = blockIdx.x * blockDim.x + threadIdx.x;
    if (i < MAXROWS) { g_as_tok[i] = 0; g_as_w[i] = 0.f; }
}

__global__ void assign_kernel() {
    int t = blockIdx.x * blockDim.x + threadIdx.x;
    if (t >= Tn) return;
#pragma unroll
    for (int k = 0; k < 2; k++) {
        int e = g_top_idx[t*2 + k];
        if (e < NE) {
            int p = atomicAdd(&g_cursor[e], 1);
            int r = g_off[e] + p;
            g_as_tok[r] = t;
            g_as_w[r] = g_top_w[t*2 + k];
        }
    }
}

// ---------------- fp16 conversion kernels ----------------

// g_x1[rj][h] = fp16(x[b][rj%SP - 2][h]), zeros for first 2 rows per batch
__global__ void expand_x1(const float* __restrict__ x) {
    size_t i = (size_t)blockIdx.x * 256 + threadIdx.x;
    if (i >= (size_t)Bb * SP * Hd / 4) return;
    size_t e = i * 4;
    int h = (int)(e & 1023);
    int rj = (int)(e >> 10);
    int r = rj % SP, b = rj / SP;
    float4 v = make_float4(0.f, 0.f, 0.f, 0.f);
    if (r >= 2) v = *(const float4*)(x + (((size_t)(b * Sq + r - 2)) << 10) + h);
    uint2* p = (uint2*)(g_x1 + (size_t)rj * KH + h);
    *p = make_uint2(pkh(__float2half(v.x), __float2half(v.y)),
                    pkh(__float2half(v.z), __float2half(v.w)));
}

// conv W: wpT[i][kk*1024 + h] = fp16(cw[i][h][kk])
__global__ void build_wpT(const float* __restrict__ cw) {
    int idx = blockIdx.x * 256 + threadIdx.x;
    if (idx >= Id * Hd * 3) return;
    int kk = idx % 3, hh = (idx / 3) & 1023, ii = idx / 3072;
    g_wpT[(size_t)ii * KC + kk * KH + hh] = __float2half(cw[(size_t)ii * 3072 + hh * 3 + kk]);
}

// suT[i][h] = fp16(suw[h][i])
__global__ void build_suT(const float* __restrict__ suw) {
    int idx = blockIdx.x * 256 + threadIdx.x;
    if (idx >= Hd * Id) return;
    int i = idx & 511, h = idx >> 9;
    g_suT[(size_t)i * KH + h] = __float2half(suw[(size_t)h * Id + i]);
}

// sdT[h][i] = fp16(sdw[i][h])
__global__ void build_sdT(const float* __restrict__ sdw) {
    int idx = blockIdx.x * 256 + threadIdx.x;
    if (idx >= Id * Hd) return;
    int h = idx & 1023, i = idx >> 10;
    g_sdT[(size_t)h * KI + i] = __float2half(sdw[(size_t)i * Hd + h]);
}

// guT[e][2i+p][h] = fp16( (p? uw : gw)[e][h][i] )
__global__ void build_guT(const float* __restrict__ gw, const float* __restrict__ uw) {
    size_t idx = (size_t)blockIdx.x * 256 + threadIdx.x;
    if (idx >= (size_t)NE * Hd * Id * 2) return;
    int p = (int)(idx & 1);
    int i = (int)((idx >> 1) & 511);
    int h = (int)((idx >> 10) & 1023);
    int e = (int)(idx >> 20);
    const float* src = p ? uw : gw;
    g_guT[((size_t)e * 1024 + 2*i + p) * KH + h] =
        __float2half(src[(((size_t)e << 10) + h) * Id + i]);
}

// dwT[e][h][i] = fp16(dw[e][i][h])
__global__ void build_dwT(const float* __restrict__ dw) {
    size_t idx = (size_t)blockIdx.x * 256 + threadIdx.x;
    if (idx >= (size_t)NE * Id * Hd) return;
    int h = (int)(idx & 1023);
    int i = (int)((idx >> 10) & 511);
    int e = (int)(idx >> 19);
    g_dwT[((size_t)e * Hd + h) * KI + i] =
        __float2half(dw[(((size_t)e << 9) + i) * Hd + h]);
}

// ---------------- mma.sync GEMM ----------------
enum { M_SH_GATE = 0, M_SH_UP, M_SH_DOWN, M_R_GU, M_R_DOWN };

template <int MODE>
__global__ void __launch_bounds__(256, 2) mmak(const float* __restrict__ X,
                                               float* __restrict__ OUT) {
    constexpr int KD = (MODE == M_SH_GATE) ? KC
                     : (MODE == M_SH_UP || MODE == M_R_GU) ? KH : KI;
    constexpr int NK = KD / 32;
    constexpr int BROWS = (MODE == M_R_GU || MODE == M_R_DOWN) ? 1024 : 0;

    int tileM = blockIdx.x, nb = blockIdx.y;
    if constexpr (MODE == M_R_GU || MODE == M_R_DOWN) {
        if (tileM >= g_ntiles) return;
    }

    __shared__ __align__(16) char smem[3 * 16384];
    unsigned smbase = smem_u32(smem);

    int tid = threadIdx.x;
    int warp = tid >> 5, lane = tid & 31;
    int wm = warp & 3, wn = warp >> 2;

    const __half* Bb_;
    if constexpr (MODE == M_SH_GATE)      Bb_ = g_wpT;
    else if constexpr (MODE == M_SH_UP)   Bb_ = g_suT;
    else if constexpr (MODE == M_SH_DOWN) Bb_ = g_sdT;
    else if constexpr (MODE == M_R_GU)    Bb_ = g_guT + (size_t)g_tile_expert[tileM] * BROWS * KD;
    else                                  Bb_ = g_dwT + (size_t)g_tile_expert[tileM] * BROWS * KD;

    int cA[2], jrow[2];
    const __half* pA[2];
    const __half* pB[2];
    unsigned oA[2], oB[2];
#pragma unroll
    for (int t = 0; t < 2; t++) {
        int id = tid + 256 * t;
        int r = id >> 2, c = id & 3;
        cA[t] = c;
        int rowg = tileM * 128 + r;
        if constexpr (MODE == M_SH_GATE || MODE == M_SH_UP) {
            int b = rowg >> 12, s = rowg & 4095;
            jrow[t] = b * SP + s;
            pA[t] = g_x1 + ((size_t)(jrow[t] + 2)) * KH + c * 8;
        } else if constexpr (MODE == M_R_GU) {
            int tok = g_as_tok[rowg];
            int jr = tok + 2 * (tok >> 12) + 2;
            pA[t] = g_x1 + (size_t)jr * KH + c * 8;
        } else if constexpr (MODE == M_SH_DOWN) {
            pA[t] = g_shact1 + (size_t)rowg * KI + c * 8;
        } else {
            pA[t] = g_act1 + (size_t)rowg * KI + c * 8;
        }
        pB[t] = Bb_ + (size_t)(nb * 128 + r) * KD + c * 8;
        unsigned sw = (unsigned)(c ^ ((r >> 1) & 3));
        oA[t] = (unsigned)(r * 64) + (sw << 4);
        oB[t] = 8192u + (unsigned)(r * 64) + (sw << 4);
    }

    auto ldst = [&](int kt, int st) {
        unsigned sb = smbase + st * 16384;
#pragma unroll
        for (int t = 0; t < 2; t++) {
            const __half* ga;
            if constexpr (MODE == M_SH_GATE) {
                int ko = kt * 32 + cA[t] * 8;
                int sh = ko >> 10;
                ga = g_x1 + (size_t)(jrow[t] + sh) * KH + (ko & 1023);
            } else {
                ga = pA[t] + kt * 32;
            }
            cpa16(sb + oA[t], ga);
            cpa16(sb + oB[t], pB[t] + kt * 32);
        }
        asm volatile("cp.async.commit_group;" ::: "memory");
    };

    float acc[2][8][4];
#pragma unroll
    for (int a = 0; a < 2; a++)
#pragma unroll
        for (int b = 0; b < 8; b++)
#pragma unroll
            for (int c = 0; c < 4; c++) acc[a][b][c] = 0.f;

    ldst(0, 0);
    ldst(1, 1);

    int idx = lane >> 3;
    int rr = (lane & 7) + 8 * (idx & 1);
    int kb = idx >> 1;

    for (int kt = 0; kt < NK; kt++) {
        int st = kt % 3;
        if (kt + 1 < NK) { asm volatile("cp.async.wait_group 1;" ::: "memory"); }
        else             { asm volatile("cp.async.wait_group 0;" ::: "memory"); }
        __syncthreads();
        if (kt + 2 < NK) ldst(kt + 2, (kt + 2) % 3);

        unsigned sA = smbase + st * 16384, sB = sA + 8192;
#pragma unroll
        for (int kc = 0; kc < 2; kc++) {
            int kch = kc * 2 + kb;
            unsigned af[2][4], bfr[4][4];
#pragma unroll
            for (int mt = 0; mt < 2; mt++) {
                int r = wm * 32 + mt * 16 + rr;
                ldsm4(af[mt], sA + r * 64 + ((unsigned)(kch ^ ((r >> 1) & 3)) << 4));
            }
#pragma unroll
            for (int nt2 = 0; nt2 < 4; nt2++) {
                int rn = wn * 64 + nt2 * 16 + rr;
                ldsm4(bfr[nt2], sB + rn * 64 + ((unsigned)(kch ^ ((rn >> 1) & 3)) << 4));
            }
#pragma unroll
            for (int mt = 0; mt < 2; mt++)
#pragma unroll
                for (int nt = 0; nt < 8; nt++)
                    mma16816(acc[mt][nt], af[mt], bfr[nt >> 1][nt & 1], bfr[nt >> 1][2 + (nt & 1)]);
        }
    }

    // ---------------- epilogue ----------------
    int l2 = lane >> 2, l4 = lane & 3;
#pragma unroll
    for (int mt = 0; mt < 2; mt++) {
#pragma unroll
        for (int hh = 0; hh < 2; hh++) {
            int rowg = tileM * 128 + wm * 32 + mt * 16 + l2 + 8 * hh;
            if constexpr (MODE == M_R_DOWN) {
                float w = g_as_w[rowg];
                if (w != 0.f) {
                    int tok = g_as_tok[rowg];
                    float* dst = OUT + (size_t)tok * Hd;
#pragma unroll
                    for (int nt = 0; nt < 8; nt++) {
                        int colg = nb * 128 + wn * 64 + nt * 8 + l4 * 2;
                        atomicAdd(dst + colg,     w * acc[mt][nt][2*hh]);
                        atomicAdd(dst + colg + 1, w * acc[mt][nt][2*hh + 1]);
                    }
                }
            } else if constexpr (MODE == M_SH_DOWN) {
                float w = g_wid[rowg];
                const float* xr = X + (size_t)rowg * Hd;
                float* dst = OUT + (size_t)rowg * Hd;
#pragma unroll
                for (int nt = 0; nt < 8; nt++) {
                    int colg = nb * 128 + wn * 64 + nt * 8 + l4 * 2;
                    float2 xv = *(const float2*)(xr + colg);
                    float2 o;
                    o.x = acc[mt][nt][2*hh]     + w * xv.x;
                    o.y = acc[mt][nt][2*hh + 1] + w * xv.y;
                    *(float2*)(dst + colg) = o;
                }
            } else if constexpr (MODE == M_SH_GATE) {
                float* dst = g_shact + (size_t)rowg * Id;
#pragma unroll
                for (int nt = 0; nt < 8; nt++) {
                    int colg = nb * 128 + wn * 64 + nt * 8 + l4 * 2;
                    *(float2*)(dst + colg) =
                        make_float2(acc[mt][nt][2*hh], acc[mt][nt][2*hh + 1]);
                }
            } else if constexpr (MODE == M_SH_UP) {
                const float* gs = g_shact + (size_t)rowg * Id;
                __half* d1 = g_shact1 + (size_t)rowg * KI;
#pragma unroll
                for (int nt = 0; nt < 8; nt++) {
                    int colg = nb * 128 + wn * 64 + nt * 8 + l4 * 2;
                    float2 g = *(const float2*)(gs + colg);
                    float v0 = silu_f(g.x) * acc[mt][nt][2*hh];
                    float v1 = silu_f(g.y) * acc[mt][nt][2*hh + 1];
                    *(unsigned*)(d1 + colg) = pkh(__float2half(v0), __float2half(v1));
                }
            } else {  // M_R_GU: interleaved (gate, up) pairs -> one value column
                __half* d1 = g_act1 + (size_t)rowg * KI;
#pragma unroll
                for (int nt = 0; nt < 8; nt++) {
                    int i = nb * 64 + wn * 32 + nt * 4 + l4;
                    float v = silu_f(acc[mt][nt][2*hh]) * acc[mt][nt][2*hh + 1];
                    d1[i] = __float2half(v);
                }
            }
        }
    }
}

// ---------------- launch ----------------
extern "C" void kernel_launch(void* const* d_in, const int* in_sizes, int n_in,
                              void* d_out, int out_size) {
    (void)in_sizes; (void)n_in; (void)out_size;
    const float* x   = (const float*)d_in[0];
    const float* rw  = (const float*)d_in[1];
    const float* rb  = (const float*)d_in[2];
    const float* gw  = (const float*)d_in[3];
    const float* uw  = (const float*)d_in[4];
    const float* dw  = (const float*)d_in[5];
    const float* cw  = (const float*)d_in[6];
    const float* suw = (const float*)d_in[7];
    const float* sdw = (const float*)d_in[8];
    float* out = (float*)d_out;

    // routing
    zero_meta<<<1, 32>>>();
    router_kernel<<<Tn / 8, 256>>>(x, rw, rb);
    prefix_kernel<<<1, 32>>>();
    fill_assign<<<(MAXROWS + 255) / 256, 256>>>();
    assign_kernel<<<Tn / 256, 256>>>();

    // fp16 conversions (no gather pass: routed GEMMs read g_x1 indirectly)
    {
        size_t n;
        n = (size_t)Bb * SP * Hd / 4;   expand_x1<<<(unsigned)((n + 255) / 256), 256>>>(x);
        n = (size_t)Id * Hd * 3;        build_wpT<<<(unsigned)((n + 255) / 256), 256>>>(cw);
        n = (size_t)Hd * Id;            build_suT<<<(unsigned)((n + 255) / 256), 256>>>(suw);
        n = (size_t)Id * Hd;            build_sdT<<<(unsigned)((n + 255) / 256), 256>>>(sdw);
        n = (size_t)NE * Hd * Id * 2;   build_guT<<<(unsigned)((n + 255) / 256), 256>>>(gw, uw);
        n = (size_t)NE * Id * Hd;       build_dwT<<<(unsigned)((n + 255) / 256), 256>>>(dw);
    }

    // shared expert: conv-gate -> up(*silu) -> down(+identity expert)
    mmak<M_SH_GATE><<<dim3(Tn / 128, Id / 128), 256>>>(x, out);
    mmak<M_SH_UP>  <<<dim3(Tn / 128, Id / 128), 256>>>(x, out);
    mmak<M_SH_DOWN><<<dim3(Tn / 128, Hd / 128), 256>>>(x, out);

    // routed experts: fused gate+up (interleaved cols), then weighted scatter down
    mmak<M_R_GU>   <<<dim3(MAX_TILES, 1024 / 128), 256>>>(x, out);
    mmak<M_R_DOWN> <<<dim3(MAX_TILES, Hd / 128), 256>>>(x, out);
}

// round 14
// speedup vs baseline: 4.5094x; 1.0650x over previous
#include <cuda_runtime.h>
#include <cuda_fp16.h>
#include <math.h>
#include <stdint.h>

#define DINLINE __device__ __forceinline__

// ---------------- problem constants ----------------
constexpr int Bb = 4;
constexpr int Sq = 4096;
constexpr int Hd = 1024;
constexpr int Id = 512;
constexpr int NE = 15;                      // routed experts (idx 15 = identity)
constexpr int Tn = Bb * Sq;                 // 16384
constexpr int SP = Sq + 2;                  // left-padded seq (conv)
constexpr int MAXROWS = 2 * Tn + NE * 128;  // 34688
constexpr int MAX_TILES = MAXROWS / 128;    // 271

// plain fp16 K sizes (single product)
constexpr int KH = Hd;         // 1024
constexpr int KI = Id;         // 512
constexpr int KC = 3 * Hd;     // 3072 (conv: 3 shifts x 1024)

// ---------------- device scratch ----------------
__device__ __align__(16) __half g_x1[(size_t)Bb * SP * KH];      // padded x fp16
__device__ __align__(16) __half g_shact1[(size_t)Tn * KI];       // shared silu*up fp16
__device__ __align__(16) __half g_act1[(size_t)MAXROWS * KI];    // routed silu*up fp16
__device__ __align__(16) float  g_shact[(size_t)Tn * Id];        // shared conv gate fp32
__device__ __align__(16) __half g_wpT[(size_t)Id * KC];          // conv W, B-layout
__device__ __align__(16) __half g_suT[(size_t)Id * KH];
__device__ __align__(16) __half g_sdT[(size_t)Hd * KI];
__device__ __align__(16) __half g_guT[(size_t)NE * 1024 * KH];   // interleaved gate/up
__device__ __align__(16) __half g_dwT[(size_t)NE * Hd * KI];

__device__ int   g_top_idx[Tn * 2];
__device__ float g_top_w[Tn * 2];
__device__ float g_wid[Tn];
__device__ int   g_counts[NE];
__device__ int   g_cursor[NE];
__device__ int   g_off[NE + 1];
__device__ int   g_tile_expert[MAX_TILES];
__device__ int   g_ntiles;
__device__ int   g_as_tok[MAXROWS];
__device__ float g_as_w[MAXROWS];

// ---------------- helpers ----------------
DINLINE float silu_f(float g) { return g / (1.f + expf(-g)); }
DINLINE unsigned pkh(__half a, __half b) {
    unsigned short ua = *(unsigned short*)&a, ub = *(unsigned short*)&b;
    return (unsigned)ua | ((unsigned)ub << 16);
}

DINLINE unsigned smem_u32(const void* p) {
    unsigned a;
    asm("{ .reg .u64 t; cvta.to.shared.u64 t, %1; cvt.u32.u64 %0, t; }" : "=r"(a) : "l"(p));
    return a;
}
DINLINE void cpa16(unsigned d, const void* g) {
    asm volatile("cp.async.cg.shared.global [%0], [%1], 16;" :: "r"(d), "l"(g) : "memory");
}
DINLINE void ldsm4(unsigned* r, unsigned a) {
    asm volatile("ldmatrix.sync.aligned.m8n8.x4.shared.b16 {%0,%1,%2,%3}, [%4];"
        : "=r"(r[0]), "=r"(r[1]), "=r"(r[2]), "=r"(r[3]) : "r"(a));
}
DINLINE void mma16816(float* c, const unsigned* a, unsigned b0, unsigned b1) {
    asm volatile(
        "mma.sync.aligned.m16n8k16.row.col.f32.f16.f16.f32 "
        "{%0,%1,%2,%3}, {%4,%5,%6,%7}, {%8,%9}, {%0,%1,%2,%3};"
        : "+f"(c[0]), "+f"(c[1]), "+f"(c[2]), "+f"(c[3])
        : "r"(a[0]), "r"(a[1]), "r"(a[2]), "r"(a[3]), "r"(b0), "r"(b1));
}

// ---------------- routing kernels ----------------
__global__ void fill_assign() {
    int i = blockIdx.x * blockDim.x + threadIdx.x;
    if (i < MAXROWS) { g_as_tok[i] = 0; g_as_w[i] = 0.f; }
    if (i < NE) { g_counts[i] = 0; g_cursor[i] = 0; }
}

__global__ void router_kernel(const float* __restrict__ x,
                              const float* __restrict__ rw,
                              const float* __restrict__ rb) {
    int gw = (blockIdx.x * blockDim.x + threadIdx.x) >> 5;
    int lane = threadIdx.x & 31;
    if (gw >= Tn) return;
    const float* xr = x + (size_t)gw * Hd;
    float acc[16];
#pragma unroll
    for (int e = 0; e < 16; e++) acc[e] = 0.f;
    for (int h = lane; h < Hd; h += 32) {
        float xv = xr[h];
        const float4* w4 = (const float4*)(rw + (size_t)h * 16);
        float4 w0 = w4[0], w1 = w4[1], w2 = w4[2], w3 = w4[3];
        acc[0] += xv*w0.x;  acc[1] += xv*w0.y;  acc[2] += xv*w0.z;  acc[3] += xv*w0.w;
        acc[4] += xv*w1.x;  acc[5] += xv*w1.y;  acc[6] += xv*w1.z;  acc[7] += xv*w1.w;
        acc[8] += xv*w2.x;  acc[9] += xv*w2.y;  acc[10]+= xv*w2.z;  acc[11]+= xv*w2.w;
        acc[12]+= xv*w3.x;  acc[13]+= xv*w3.y;  acc[14]+= xv*w3.z;  acc[15]+= xv*w3.w;
    }
#pragma unroll
    for (int e = 0; e < 16; e++) {
#pragma unroll
        for (int o = 16; o > 0; o >>= 1) acc[e] += __shfl_xor_sync(0xffffffffu, acc[e], o);
    }
    if (lane == 0) {
        float l[16]; float m = -1e30f;
#pragma unroll
        for (int e = 0; e < 16; e++) { l[e] = acc[e] + rb[e]; m = fmaxf(m, l[e]); }
        float p[16]; float s = 0.f;
#pragma unroll
        for (int e = 0; e < 16; e++) { p[e] = expf(l[e] - m); s += p[e]; }
        int i1 = 0; float p1 = p[0];
#pragma unroll
        for (int e = 1; e < 16; e++) if (p[e] > p1) { p1 = p[e]; i1 = e; }
        int i2 = -1; float p2 = -1e30f;
#pragma unroll
        for (int e = 0; e < 16; e++) if (e != i1 && p[e] > p2) { p2 = p[e]; i2 = e; }
        float pr1 = p1 / s, pr2 = p2 / s;
        float d = pr1 + pr2 + 1e-6f;
        float w1 = pr1 / d, w2 = pr2 / d;
        g_top_idx[gw*2] = i1; g_top_idx[gw*2+1] = i2;
        g_top_w[gw*2] = w1;   g_top_w[gw*2+1] = w2;
        float wid = 0.f;
        if (i1 == NE) wid = w1; else if (i2 == NE) wid = w2;
        g_wid[gw] = wid;
        if (i1 < NE) atomicAdd(&g_counts[i1], 1);
        if (i2 < NE) atomicAdd(&g_counts[i2], 1);
    }
}

__global__ void prefix_kernel() {
    if (threadIdx.x == 0 && blockIdx.x == 0) {
        int off = 0;
        for (int e = 0; e < NE; e++) {
            g_off[e] = off;
            int a = (g_counts[e] + 127) & ~127;
            for (int t = off >> 7; t < (off + a) >> 7; t++) g_tile_expert[t] = e;
            off += a;
        }
        g_off[NE] = off;
        g_ntiles = off >> 7;
    }
}

__global__ void assign_kernel() {
    int t = blockIdx.x * blockDim.x + threadIdx.x;
    if (t >= Tn) return;
#pragma unroll
    for (int k = 0; k < 2; k++) {
        int e = g_top_idx[t*2 + k];
        if (e < NE) {
            int p = atomicAdd(&g_cursor[e], 1);
            int r = g_off[e] + p;
            g_as_tok[r] = t;
            g_as_w[r] = g_top_w[t*2 + k];
        }
    }
}

// ---------------- fp16 conversion kernels ----------------

// g_x1[rj][h] = fp16(x[b][rj%SP - 2][h]), zeros for first 2 rows per batch
__global__ void expand_x1(const float* __restrict__ x) {
    size_t i = (size_t)blockIdx.x * 256 + threadIdx.x;
    if (i >= (size_t)Bb * SP * Hd / 4) return;
    size_t e = i * 4;
    int h = (int)(e & 1023);
    int rj = (int)(e >> 10);
    int r = rj % SP, b = rj / SP;
    float4 v = make_float4(0.f, 0.f, 0.f, 0.f);
    if (r >= 2) v = *(const float4*)(x + (((size_t)(b * Sq + r - 2)) << 10) + h);
    uint2* p = (uint2*)(g_x1 + (size_t)rj * KH + h);
    *p = make_uint2(pkh(__float2half(v.x), __float2half(v.y)),
                    pkh(__float2half(v.z), __float2half(v.w)));
}

// conv W: wpT[i][kk*1024 + h] = fp16(cw[i][h][kk])
__global__ void build_wpT(const float* __restrict__ cw) {
    int idx = blockIdx.x * 256 + threadIdx.x;
    if (idx >= Id * Hd * 3) return;
    int kk = idx % 3, hh = (idx / 3) & 1023, ii = idx / 3072;
    g_wpT[(size_t)ii * KC + kk * KH + hh] = __float2half(cw[(size_t)ii * 3072 + hh * 3 + kk]);
}

// suT[i][h] = fp16(suw[h][i])
__global__ void build_suT(const float* __restrict__ suw) {
    int idx = blockIdx.x * 256 + threadIdx.x;
    if (idx >= Hd * Id) return;
    int i = idx & 511, h = idx >> 9;
    g_suT[(size_t)i * KH + h] = __float2half(suw[(size_t)h * Id + i]);
}

// sdT[h][i] = fp16(sdw[i][h])
__global__ void build_sdT(const float* __restrict__ sdw) {
    int idx = blockIdx.x * 256 + threadIdx.x;
    if (idx >= Id * Hd) return;
    int h = idx & 1023, i = idx >> 10;
    g_sdT[(size_t)h * KI + i] = __float2half(sdw[(size_t)i * Hd + h]);
}

// guT[e][2i+p][h] = fp16( (p? uw : gw)[e][h][i] )
__global__ void build_guT(const float* __restrict__ gw, const float* __restrict__ uw) {
    size_t idx = (size_t)blockIdx.x * 256 + threadIdx.x;
    if (idx >= (size_t)NE * Hd * Id * 2) return;
    int p = (int)(idx & 1);
    int i = (int)((idx >> 1) & 511);
    int h = (int)((idx >> 10) & 1023);
    int e = (int)(idx >> 20);
    const float* src = p ? uw : gw;
    g_guT[((size_t)e * 1024 + 2*i + p) * KH + h] =
        __float2half(src[(((size_t)e << 10) + h) * Id + i]);
}

// dwT[e][h][i] = fp16(dw[e][i][h])
__global__ void build_dwT(const float* __restrict__ dw) {
    size_t idx = (size_t)blockIdx.x * 256 + threadIdx.x;
    if (idx >= (size_t)NE * Id * Hd) return;
    int h = (int)(idx & 1023);
    int i = (int)((idx >> 10) & 511);
    int e = (int)(idx >> 19);
    g_dwT[((size_t)e * Hd + h) * KI + i] =
        __float2half(dw[(((size_t)e << 9) + i) * Hd + h]);
}

// ---------------- mma.sync GEMM ----------------
enum { M_SH_GATE = 0, M_SH_UP, M_SH_DOWN, M_R_GU, M_R_DOWN };

template <int MODE>
__global__ void __launch_bounds__(256, 2) mmak(const float* __restrict__ X,
                                               float* __restrict__ OUT) {
    constexpr int KD = (MODE == M_SH_GATE) ? KC
                     : (MODE == M_SH_UP || MODE == M_R_GU) ? KH : KI;
    constexpr int NK = KD / 32;
    constexpr int BROWS = (MODE == M_R_GU || MODE == M_R_DOWN) ? 1024 : 0;

    int tileM = blockIdx.x, nb = blockIdx.y;
    if constexpr (MODE == M_R_GU || MODE == M_R_DOWN) {
        if (tileM >= g_ntiles) return;
    }

    __shared__ __align__(16) char smem[3 * 16384];
    unsigned smbase = smem_u32(smem);

    int tid = threadIdx.x;
    int warp = tid >> 5, lane = tid & 31;
    int wm = warp & 3, wn = warp >> 2;

    const __half* Bb_;
    if constexpr (MODE == M_SH_GATE)      Bb_ = g_wpT;
    else if constexpr (MODE == M_SH_UP)   Bb_ = g_suT;
    else if constexpr (MODE == M_SH_DOWN) Bb_ = g_sdT;
    else if constexpr (MODE == M_R_GU)    Bb_ = g_guT + (size_t)g_tile_expert[tileM] * BROWS * KD;
    else                                  Bb_ = g_dwT + (size_t)g_tile_expert[tileM] * BROWS * KD;

    int cA[2], jrow[2];
    const __half* pA[2];
    const __half* pB[2];
    unsigned oA[2], oB[2];
#pragma unroll
    for (int t = 0; t < 2; t++) {
        int id = tid + 256 * t;
        int r = id >> 2, c = id & 3;
        cA[t] = c;
        int rowg = tileM * 128 + r;
        if constexpr (MODE == M_SH_GATE || MODE == M_SH_UP) {
            int b = rowg >> 12, s = rowg & 4095;
            jrow[t] = b * SP + s;
            pA[t] = g_x1 + ((size_t)(jrow[t] + 2)) * KH + c * 8;
        } else if constexpr (MODE == M_R_GU) {
            int tok = g_as_tok[rowg];
            int jr = tok + 2 * (tok >> 12) + 2;
            pA[t] = g_x1 + (size_t)jr * KH + c * 8;
        } else if constexpr (MODE == M_SH_DOWN) {
            pA[t] = g_shact1 + (size_t)rowg * KI + c * 8;
        } else {
            pA[t] = g_act1 + (size_t)rowg * KI + c * 8;
        }
        pB[t] = Bb_ + (size_t)(nb * 128 + r) * KD + c * 8;
        unsigned sw = (unsigned)(c ^ ((r >> 1) & 3));
        oA[t] = (unsigned)(r * 64) + (sw << 4);
        oB[t] = 8192u + (unsigned)(r * 64) + (sw << 4);
    }

    auto ldst = [&](int kt, int st) {
        unsigned sb = smbase + st * 16384;
#pragma unroll
        for (int t = 0; t < 2; t++) {
            const __half* ga;
            if constexpr (MODE == M_SH_GATE) {
                int ko = kt * 32 + cA[t] * 8;
                int sh = ko >> 10;
                ga = g_x1 + (size_t)(jrow[t] + sh) * KH + (ko & 1023);
            } else {
                ga = pA[t] + kt * 32;
            }
            cpa16(sb + oA[t], ga);
            cpa16(sb + oB[t], pB[t] + kt * 32);
        }
        asm volatile("cp.async.commit_group;" ::: "memory");
    };

    float acc[2][8][4];
#pragma unroll
    for (int a = 0; a < 2; a++)
#pragma unroll
        for (int b = 0; b < 8; b++)
#pragma unroll
            for (int c = 0; c < 4; c++) acc[a][b][c] = 0.f;

    ldst(0, 0);
    ldst(1, 1);

    int idx = lane >> 3;
    int rr = (lane & 7) + 8 * (idx & 1);
    int kb = idx >> 1;

    for (int kt = 0; kt < NK; kt++) {
        int st = kt % 3;
        if (kt + 1 < NK) { asm volatile("cp.async.wait_group 1;" ::: "memory"); }
        else             { asm volatile("cp.async.wait_group 0;" ::: "memory"); }
        __syncthreads();
        if (kt + 2 < NK) ldst(kt + 2, (kt + 2) % 3);

        unsigned sA = smbase + st * 16384, sB = sA + 8192;
#pragma unroll
        for (int kc = 0; kc < 2; kc++) {
            int kch = kc * 2 + kb;
            unsigned af[2][4], bfr[4][4];
#pragma unroll
            for (int mt = 0; mt < 2; mt++) {
                int r = wm * 32 + mt * 16 + rr;
                ldsm4(af[mt], sA + r * 64 + ((unsigned)(kch ^ ((r >> 1) & 3)) << 4));
            }
#pragma unroll
            for (int nt2 = 0; nt2 < 4; nt2++) {
                int rn = wn * 64 + nt2 * 16 + rr;
                ldsm4(bfr[nt2], sB + rn * 64 + ((unsigned)(kch ^ ((rn >> 1) & 3)) << 4));
            }
#pragma unroll
            for (int mt = 0; mt < 2; mt++)
#pragma unroll
                for (int nt = 0; nt < 8; nt++)
                    mma16816(acc[mt][nt], af[mt], bfr[nt >> 1][nt & 1], bfr[nt >> 1][2 + (nt & 1)]);
        }
    }

    // ---------------- epilogue ----------------
    int l2 = lane >> 2, l4 = lane & 3;
#pragma unroll
    for (int mt = 0; mt < 2; mt++) {
#pragma unroll
        for (int hh = 0; hh < 2; hh++) {
            int rowg = tileM * 128 + wm * 32 + mt * 16 + l2 + 8 * hh;
            if constexpr (MODE == M_R_DOWN) {
                float w = g_as_w[rowg];
                if (w != 0.f) {
                    int tok = g_as_tok[rowg];
                    float* dst = OUT + (size_t)tok * Hd;
#pragma unroll
                    for (int nt = 0; nt < 8; nt++) {
                        int colg = nb * 128 + wn * 64 + nt * 8 + l4 * 2;
                        atomicAdd(dst + colg,     w * acc[mt][nt][2*hh]);
                        atomicAdd(dst + colg + 1, w * acc[mt][nt][2*hh + 1]);
                    }
                }
            } else if constexpr (MODE == M_SH_DOWN) {
                float w = g_wid[rowg];
                const float* xr = X + (size_t)rowg * Hd;
                float* dst = OUT + (size_t)rowg * Hd;
#pragma unroll
                for (int nt = 0; nt < 8; nt++) {
                    int colg = nb * 128 + wn * 64 + nt * 8 + l4 * 2;
                    float2 xv = *(const float2*)(xr + colg);
                    float2 o;
                    o.x = acc[mt][nt][2*hh]     + w * xv.x;
                    o.y = acc[mt][nt][2*hh + 1] + w * xv.y;
                    *(float2*)(dst + colg) = o;
                }
            } else if constexpr (MODE == M_SH_GATE) {
                float* dst = g_shact + (size_t)rowg * Id;
#pragma unroll
                for (int nt = 0; nt < 8; nt++) {
                    int colg = nb * 128 + wn * 64 + nt * 8 + l4 * 2;
                    *(float2*)(dst + colg) =
                        make_float2(acc[mt][nt][2*hh], acc[mt][nt][2*hh + 1]);
                }
            } else if constexpr (MODE == M_SH_UP) {
                const float* gs = g_shact + (size_t)rowg * Id;
                __half* d1 = g_shact1 + (size_t)rowg * KI;
#pragma unroll
                for (int nt = 0; nt < 8; nt++) {
                    int colg = nb * 128 + wn * 64 + nt * 8 + l4 * 2;
                    float2 g = *(const float2*)(gs + colg);
                    float v0 = silu_f(g.x) * acc[mt][nt][2*hh];
                    float v1 = silu_f(g.y) * acc[mt][nt][2*hh + 1];
                    *(unsigned*)(d1 + colg) = pkh(__float2half(v0), __float2half(v1));
                }
            } else {  // M_R_GU: interleaved (gate, up) pairs -> one value column
                __half* d1 = g_act1 + (size_t)rowg * KI;
#pragma unroll
                for (int nt = 0; nt < 8; nt++) {
                    int i = nb * 64 + wn * 32 + nt * 4 + l4;
                    float v = silu_f(acc[mt][nt][2*hh]) * acc[mt][nt][2*hh + 1];
                    d1[i] = __float2half(v);
                }
            }
        }
    }
}

// ---------------- launch: fork-join DAG over 3 streams ----------------
extern "C" void kernel_launch(void* const* d_in, const int* in_sizes, int n_in,
                              void* d_out, int out_size) {
    (void)in_sizes; (void)n_in; (void)out_size;
    const float* x   = (const float*)d_in[0];
    const float* rw  = (const float*)d_in[1];
    const float* rb  = (const float*)d_in[2];
    const float* gw  = (const float*)d_in[3];
    const float* uw  = (const float*)d_in[4];
    const float* dw  = (const float*)d_in[5];
    const float* cw  = (const float*)d_in[6];
    const float* suw = (const float*)d_in[7];
    const float* sdw = (const float*)d_in[8];
    float* out = (float*)d_out;

    // persistent side streams / events: created once on the first
    // (uncaptured, correctness) call; reused by every later call so the
    // captured work is identical on all calls.
    static cudaStream_t s1 = nullptr, s2 = nullptr;
    static cudaEvent_t eF = nullptr, eX1 = nullptr, eW2 = nullptr,
                       eRt = nullptr, eShD = nullptr;
    if (s1 == nullptr) {
        cudaStreamCreateWithFlags(&s1, cudaStreamNonBlocking);
        cudaStreamCreateWithFlags(&s2, cudaStreamNonBlocking);
        cudaEventCreateWithFlags(&eF,   cudaEventDisableTiming);
        cudaEventCreateWithFlags(&eX1,  cudaEventDisableTiming);
        cudaEventCreateWithFlags(&eW2,  cudaEventDisableTiming);
        cudaEventCreateWithFlags(&eRt,  cudaEventDisableTiming);
        cudaEventCreateWithFlags(&eShD, cudaEventDisableTiming);
    }

    // fork
    cudaEventRecord(eF, 0);
    cudaStreamWaitEvent(s1, eF, 0);
    cudaStreamWaitEvent(s2, eF, 0);

    // s2: routed-expert weight conversions (independent of everything)
    {
        size_t n;
        n = (size_t)NE * Hd * Id * 2;  build_guT<<<(unsigned)((n + 255) / 256), 256, 0, s2>>>(gw, uw);
        n = (size_t)NE * Id * Hd;      build_dwT<<<(unsigned)((n + 255) / 256), 256, 0, s2>>>(dw);
    }
    cudaEventRecord(eW2, s2);

    // s1: x conversion + shared-expert chain
    {
        size_t n;
        n = (size_t)Bb * SP * Hd / 4;  expand_x1<<<(unsigned)((n + 255) / 256), 256, 0, s1>>>(x);
        cudaEventRecord(eX1, s1);
        n = (size_t)Id * Hd * 3;       build_wpT<<<(unsigned)((n + 255) / 256), 256, 0, s1>>>(cw);
        n = (size_t)Hd * Id;           build_suT<<<(unsigned)((n + 255) / 256), 256, 0, s1>>>(suw);
        n = (size_t)Id * Hd;           build_sdT<<<(unsigned)((n + 255) / 256), 256, 0, s1>>>(sdw);
    }
    mmak<M_SH_GATE><<<dim3(Tn / 128, Id / 128), 256, 0, s1>>>(x, out);
    mmak<M_SH_UP>  <<<dim3(Tn / 128, Id / 128), 256, 0, s1>>>(x, out);

    // s0 (capture stream): routing chain
    fill_assign<<<(MAXROWS + 255) / 256, 256>>>();
    router_kernel<<<Tn / 8, 256>>>(x, rw, rb);
    cudaEventRecord(eRt, 0);
    prefix_kernel<<<1, 32>>>();
    assign_kernel<<<Tn / 256, 256>>>();

    // s1: SH_DOWN needs g_wid from the router
    cudaStreamWaitEvent(s1, eRt, 0);
    mmak<M_SH_DOWN><<<dim3(Tn / 128, Hd / 128), 256, 0, s1>>>(x, out);
    cudaEventRecord(eShD, s1);

    // s0: routed chain (needs x1 + guT; R_DOWN needs OUT initialized by SH_DOWN)
    cudaStreamWaitEvent(0, eX1, 0);
    cudaStreamWaitEvent(0, eW2, 0);
    mmak<M_R_GU>  <<<dim3(MAX_TILES, 1024 / 128), 256>>>(x, out);
    cudaStreamWaitEvent(0, eShD, 0);
    mmak<M_R_DOWN><<<dim3(MAX_TILES, Hd / 128), 256>>>(x, out);
    // all side streams joined into s0 via eW2 / eShD waits above
}